// round 1
// baseline (speedup 1.0000x reference)
#include <cuda_runtime.h>
#include <math.h>

#define Lc 4
#define Bc 4
#define Nc 2048
#define Dc 512
#define Hc 8
#define HDc 64
#define Mrows (Bc*Nc)   // 8192

// ---- scratch (no allocs allowed; __device__ globals are the sanctioned path) ----
__device__ float g_y[Mrows*Dc];
__device__ float g_q[Mrows*Dc];
__device__ float g_k[Mrows*Dc];
__device__ float g_v[Mrows*Dc];
__device__ float g_o[Mrows*Dc];
__device__ float g_t[Mrows*Dc];

__device__ __forceinline__ float gelu_exact(float x) {
    return 0.5f * x * (1.0f + erff(x * 0.70710678118654752f));
}

// ---------------- LayerNorm: one block per row of 512 ----------------
__global__ __launch_bounds__(128) void ln_kernel(const float* __restrict__ hin,
                                                 const float* __restrict__ gg,
                                                 const float* __restrict__ bb,
                                                 float* __restrict__ y) {
    const int row = blockIdx.x;
    const int t = threadIdx.x;
    const float4 v = ((const float4*)(hin + (size_t)row * Dc))[t];
    float s  = v.x + v.y + v.z + v.w;
    float ss = v.x*v.x + v.y*v.y + v.z*v.z + v.w*v.w;
    #pragma unroll
    for (int o = 16; o > 0; o >>= 1) {
        s  += __shfl_xor_sync(0xFFFFFFFFu, s, o);
        ss += __shfl_xor_sync(0xFFFFFFFFu, ss, o);
    }
    __shared__ float sh[8];
    const int w = t >> 5;
    if ((t & 31) == 0) { sh[w] = s; sh[4 + w] = ss; }
    __syncthreads();
    const float st  = sh[0] + sh[1] + sh[2] + sh[3];
    const float sst = sh[4] + sh[5] + sh[6] + sh[7];
    const float mu  = st * (1.0f / Dc);
    const float var = sst * (1.0f / Dc) - mu * mu;
    const float inv = rsqrtf(var + 1e-5f);
    const float4 g4 = ((const float4*)gg)[t];
    const float4 b4 = ((const float4*)bb)[t];
    float4 r;
    r.x = (v.x - mu) * inv * g4.x + b4.x;
    r.y = (v.y - mu) * inv * g4.y + b4.y;
    r.z = (v.z - mu) * inv * g4.z + b4.z;
    r.w = (v.w - mu) * inv * g4.w + b4.w;
    ((float4*)(y + (size_t)row * Dc))[t] = r;
}

// ---------------- SGEMM: C[M=8192, 512] = A @ W  (+epilogue) ----------------
// OP 0: C = acc
// OP 1: C = resid + acc + bias
// OP 2: C = gelu(acc + bias)
template <int OP>
__global__ __launch_bounds__(256) void gemm512(const float* __restrict__ A,
                                               const float* __restrict__ W,
                                               const float* __restrict__ bias,
                                               const float* __restrict__ resid,
                                               float* __restrict__ C) {
    __shared__ __align__(16) float As[16][68];  // [k][m], padded (bank + f4 align)
    __shared__ __align__(16) float Bs[16][64];  // [k][n]

    const int tid = threadIdx.x;
    const int tx = tid & 15;
    const int ty = tid >> 4;
    const int m0 = blockIdx.y * 64;
    const int n0 = blockIdx.x * 64;

    const int ar = tid >> 2, avc = tid & 3;   // A: 64 rows x 4 f4-cols
    const int br = tid >> 4, bvc = tid & 15;  // W: 16 rows x 16 f4-cols

    const float* Aptr = A + (size_t)(m0 + ar) * Dc + avc * 4;
    const float* Wptr = W + (size_t)br * Dc + n0 + bvc * 4;

    float acc[4][4] = {};

    for (int kt = 0; kt < Dc / 16; kt++) {
        const float4 a4 = *(const float4*)(Aptr + kt * 16);
        const float4 b4 = *(const float4*)(Wptr + (size_t)kt * 16 * Dc);
        As[avc * 4 + 0][ar] = a4.x;
        As[avc * 4 + 1][ar] = a4.y;
        As[avc * 4 + 2][ar] = a4.z;
        As[avc * 4 + 3][ar] = a4.w;
        *(float4*)&Bs[br][bvc * 4] = b4;
        __syncthreads();
        #pragma unroll
        for (int k = 0; k < 16; k++) {
            const float4 av = *(const float4*)&As[k][ty * 4];
            const float4 bv = *(const float4*)&Bs[k][tx * 4];
            const float a[4] = {av.x, av.y, av.z, av.w};
            const float b[4] = {bv.x, bv.y, bv.z, bv.w};
            #pragma unroll
            for (int i = 0; i < 4; i++)
                #pragma unroll
                for (int j = 0; j < 4; j++)
                    acc[i][j] = fmaf(a[i], b[j], acc[i][j]);
        }
        __syncthreads();
    }

    const int row = m0 + ty * 4;
    const int col = n0 + tx * 4;
    float4 bias4;
    if (OP != 0) bias4 = *(const float4*)(bias + col);
    #pragma unroll
    for (int i = 0; i < 4; i++) {
        float4 r;
        if (OP == 0) {
            r.x = acc[i][0]; r.y = acc[i][1]; r.z = acc[i][2]; r.w = acc[i][3];
        } else if (OP == 1) {
            const float4 rs = *(const float4*)(resid + (size_t)(row + i) * Dc + col);
            r.x = rs.x + acc[i][0] + bias4.x;
            r.y = rs.y + acc[i][1] + bias4.y;
            r.z = rs.z + acc[i][2] + bias4.z;
            r.w = rs.w + acc[i][3] + bias4.w;
        } else {
            r.x = gelu_exact(acc[i][0] + bias4.x);
            r.y = gelu_exact(acc[i][1] + bias4.y);
            r.z = gelu_exact(acc[i][2] + bias4.z);
            r.w = gelu_exact(acc[i][3] + bias4.w);
        }
        *(float4*)(C + (size_t)(row + i) * Dc + col) = r;
    }
}

// ---------------- Flash attention: 1 thread = 1 query row, Tk=32 ----------------
// reads g_q,g_k,g_v; writes g_o.  grid = (16 qtiles, 8 heads, 4 batch), 128 thr.
__global__ __launch_bounds__(128) void attn_kernel() {
    const int qt = blockIdx.x, hh = blockIdx.y, bb = blockIdx.z;
    const int tid = threadIdx.x;
    const int qi = qt * 128 + tid;

    __shared__ __align__(16) float Ks[32][68];
    __shared__ __align__(16) float Vs[32][68];
    __shared__ float Ss[128][33];

    const float scale = 0.044194173824159216f; // 512^-0.5 (ref uses D, not HD)

    float q[HDc], o[HDc];
    {
        const float* qp = g_q + ((size_t)(bb * Nc + qi)) * Dc + hh * HDc;
        #pragma unroll
        for (int d4 = 0; d4 < HDc / 4; d4++) {
            const float4 v = ((const float4*)qp)[d4];
            q[d4 * 4 + 0] = v.x * scale;
            q[d4 * 4 + 1] = v.y * scale;
            q[d4 * 4 + 2] = v.z * scale;
            q[d4 * 4 + 3] = v.w * scale;
        }
    }
    #pragma unroll
    for (int d = 0; d < HDc; d++) o[d] = 0.0f;
    float m = -1e30f, l = 0.0f;

    for (int kt = 0; kt < Nc / 32; kt++) {
        __syncthreads();  // previous tile's Ks/Vs fully consumed
        for (int idx = tid; idx < 32 * 16; idx += 128) {
            const int r = idx >> 4, c = idx & 15;
            const size_t base = ((size_t)(bb * Nc + kt * 32 + r)) * Dc + hh * HDc + c * 4;
            *(float4*)&Ks[r][c * 4] = *(const float4*)(g_k + base);
            *(float4*)&Vs[r][c * 4] = *(const float4*)(g_v + base);
        }
        __syncthreads();

        // pass 1: scores for this thread's row + tile max
        float tm = m;
        for (int j = 0; j < 32; j++) {
            float a0 = 0.f, a1 = 0.f, a2 = 0.f, a3 = 0.f;
            #pragma unroll
            for (int d = 0; d < HDc; d += 4) {
                a0 = fmaf(q[d + 0], Ks[j][d + 0], a0);
                a1 = fmaf(q[d + 1], Ks[j][d + 1], a1);
                a2 = fmaf(q[d + 2], Ks[j][d + 2], a2);
                a3 = fmaf(q[d + 3], Ks[j][d + 3], a3);
            }
            const float s = (a0 + a1) + (a2 + a3);
            Ss[tid][j] = s;
            tm = fmaxf(tm, s);
        }

        // pass 2: online softmax rescale + PV accumulate
        const float corr = __expf(m - tm);
        m = tm;
        l *= corr;
        #pragma unroll
        for (int d = 0; d < HDc; d++) o[d] *= corr;
        for (int j = 0; j < 32; j++) {
            const float p = __expf(Ss[tid][j] - m);
            l += p;
            #pragma unroll
            for (int d = 0; d < HDc; d++) o[d] = fmaf(p, Vs[j][d], o[d]);
        }
    }

    const float invl = 1.0f / l;
    float* op = g_o + ((size_t)(bb * Nc + qi)) * Dc + hh * HDc;
    #pragma unroll
    for (int d4 = 0; d4 < HDc / 4; d4++) {
        float4 r;
        r.x = o[d4 * 4 + 0] * invl;
        r.y = o[d4 * 4 + 1] * invl;
        r.z = o[d4 * 4 + 2] * invl;
        r.w = o[d4 * 4 + 3] * invl;
        ((float4*)op)[d4] = r;
    }
}

// ---------------- driver ----------------
extern "C" void kernel_launch(void* const* d_in, const int* in_sizes, int n_in,
                              void* d_out, int out_size) {
    const float* x    = (const float*)d_in[0];
    const float* Wq   = (const float*)d_in[1];
    const float* Wk   = (const float*)d_in[2];
    const float* Wv   = (const float*)d_in[3];
    const float* Wo   = (const float*)d_in[4];
    const float* bo   = (const float*)d_in[5];
    const float* ln1g = (const float*)d_in[6];
    const float* ln1b = (const float*)d_in[7];
    const float* W1   = (const float*)d_in[8];
    const float* b1   = (const float*)d_in[9];
    const float* W2   = (const float*)d_in[10];
    const float* b2   = (const float*)d_in[11];
    const float* ln2g = (const float*)d_in[12];
    const float* ln2b = (const float*)d_in[13];
    float* h = (float*)d_out;

    float *py, *pq, *pk, *pv, *po, *pt;
    cudaGetSymbolAddress((void**)&py, g_y);
    cudaGetSymbolAddress((void**)&pq, g_q);
    cudaGetSymbolAddress((void**)&pk, g_k);
    cudaGetSymbolAddress((void**)&pv, g_v);
    cudaGetSymbolAddress((void**)&po, g_o);
    cudaGetSymbolAddress((void**)&pt, g_t);

    cudaMemcpyAsync(h, x, sizeof(float) * (size_t)Mrows * Dc, cudaMemcpyDeviceToDevice);

    const dim3 gB(Dc / 64, Mrows / 64);  // (8, 128)
    for (int l = 0; l < Lc; l++) {
        const size_t wo_off = (size_t)l * Dc * Dc;
        const float* wq = Wq + wo_off;
        const float* wk = Wk + wo_off;
        const float* wv = Wv + wo_off;
        const float* wo = Wo + wo_off;
        const float* w1 = W1 + wo_off;
        const float* w2 = W2 + wo_off;

        ln_kernel<<<Mrows, 128>>>(h, ln1g + l * Dc, ln1b + l * Dc, py);
        gemm512<0><<<gB, 256>>>(py, wq, nullptr, nullptr, pq);
        gemm512<0><<<gB, 256>>>(py, wk, nullptr, nullptr, pk);
        gemm512<0><<<gB, 256>>>(py, wv, nullptr, nullptr, pv);
        attn_kernel<<<dim3(Nc / 128, Hc, Bc), 128>>>();
        gemm512<1><<<gB, 256>>>(po, wo, bo + l * Dc, h, h);
        ln_kernel<<<Mrows, 128>>>(h, ln2g + l * Dc, ln2b + l * Dc, py);
        gemm512<2><<<gB, 256>>>(py, w1, b1 + l * Dc, nullptr, pt);
        gemm512<1><<<gB, 256>>>(pt, w2, b2 + l * Dc, h, h);
    }
}

// round 2
// speedup vs baseline: 2.9192x; 2.9192x over previous
#include <cuda_runtime.h>
#include <math.h>
#include <stdint.h>

#define Lc 4
#define Bc 4
#define Nc 2048
#define Dc 512
#define Hc 8
#define HDc 64
#define Mrows (Bc*Nc)   // 8192

// ---------------- scratch ----------------
__device__ float g_y[Mrows*Dc];
__device__ float g_q[Mrows*Dc];
__device__ float g_k[Mrows*Dc];
__device__ float g_v[Mrows*Dc];
__device__ float g_o[Mrows*Dc];
__device__ float g_t[Mrows*Dc];
__device__ float g_s[(size_t)Bc*Hc*Nc*Nc];        // 537MB score/prob buffer
__device__ float g_wr[6*Lc*Dc*Dc];                // tf32-rounded weights (25MB)

__device__ __forceinline__ float rtf32(float x) {
    uint32_t u;
    asm("cvt.rna.tf32.f32 %0, %1;" : "=r"(u) : "f"(x));
    return __uint_as_float(u);
}
__device__ __forceinline__ float gelu_exact(float x) {
    return 0.5f * x * (1.0f + erff(x * 0.70710678118654752f));
}
__device__ __forceinline__ void cpasync16(void* sdst, const void* gsrc) {
    uint32_t s = (uint32_t)__cvta_generic_to_shared(sdst);
    asm volatile("cp.async.cg.shared.global [%0], [%1], 16;" :: "r"(s), "l"(gsrc));
}
__device__ __forceinline__ void mma_tf32(float* d, const uint32_t* a, const uint32_t* b) {
    asm volatile("mma.sync.aligned.m16n8k8.row.col.f32.tf32.tf32.f32 "
                 "{%0,%1,%2,%3}, {%4,%5,%6,%7}, {%8,%9}, {%0,%1,%2,%3};"
                 : "+f"(d[0]), "+f"(d[1]), "+f"(d[2]), "+f"(d[3])
                 : "r"(a[0]), "r"(a[1]), "r"(a[2]), "r"(a[3]), "r"(b[0]), "r"(b[1]));
}

// ---------------- weight rounding (once per call) ----------------
__global__ __launch_bounds__(256) void round_kernel(const float* __restrict__ in,
                                                    float* __restrict__ out) {
    const int i = blockIdx.x * 256 + threadIdx.x;
    const float4 v = ((const float4*)in)[i];
    float4 r;
    r.x = rtf32(v.x); r.y = rtf32(v.y); r.z = rtf32(v.z); r.w = rtf32(v.w);
    ((float4*)out)[i] = r;
}

// ---------------- LayerNorm (output rounded to tf32 grid) ----------------
__global__ __launch_bounds__(128) void ln_kernel(const float* __restrict__ hin,
                                                 const float* __restrict__ gg,
                                                 const float* __restrict__ bb,
                                                 float* __restrict__ y) {
    const int row = blockIdx.x;
    const int t = threadIdx.x;
    const float4 v = ((const float4*)(hin + (size_t)row * Dc))[t];
    float s  = v.x + v.y + v.z + v.w;
    float ss = v.x*v.x + v.y*v.y + v.z*v.z + v.w*v.w;
    #pragma unroll
    for (int o = 16; o > 0; o >>= 1) {
        s  += __shfl_xor_sync(0xFFFFFFFFu, s, o);
        ss += __shfl_xor_sync(0xFFFFFFFFu, ss, o);
    }
    __shared__ float sh[8];
    const int w = t >> 5;
    if ((t & 31) == 0) { sh[w] = s; sh[4 + w] = ss; }
    __syncthreads();
    const float st  = sh[0] + sh[1] + sh[2] + sh[3];
    const float sst = sh[4] + sh[5] + sh[6] + sh[7];
    const float mu  = st * (1.0f / Dc);
    const float var = sst * (1.0f / Dc) - mu * mu;
    const float inv = rsqrtf(var + 1e-5f);
    const float4 g4 = ((const float4*)gg)[t];
    const float4 b4 = ((const float4*)bb)[t];
    float4 r;
    r.x = rtf32((v.x - mu) * inv * g4.x + b4.x);
    r.y = rtf32((v.y - mu) * inv * g4.y + b4.y);
    r.z = rtf32((v.z - mu) * inv * g4.z + b4.z);
    r.w = rtf32((v.w - mu) * inv * g4.w + b4.w);
    ((float4*)(y + (size_t)row * Dc))[t] = r;
}

// ---------------- pipelined tf32 MMA GEMM ----------------
// C[M,BN-grid] = A[M,K] @ B[K,N].  BM=128, BK=32.  8 warps as 4x2.
// OP 0: C = acc ; OP 1: C = resid + acc + bias ; OP 2: C = gelu(acc + bias)
// RND: round output to tf32 grid (for values feeding another GEMM as input)
template <int BN, int OP, int RND>
__global__ __launch_bounds__(256)
void gemm_pipe(const float* __restrict__ A, int lda,
               const float* __restrict__ Bm, int ldb,
               float* __restrict__ C, int ldc, int K,
               const float* __restrict__ bias, const float* __restrict__ resid,
               long aO, long aI, long bO, long bI, long cO, long cI) {
    constexpr int BM = 128, BK = 32;
    constexpr int AS = BK + 4;     // 36  (A row stride, words)
    constexpr int BS = BN + 8;     // B row stride, words
    constexpr int NI = BN / 16;    // n-atoms per warp (warp tile n = BN/2)
    extern __shared__ float smem[];
    float* As = smem;                        // [2][BM][AS]
    float* Bs = smem + 2 * BM * AS;          // [2][BK][BS]

    const int z = blockIdx.z;
    const long aoff = (long)(z >> 3) * aO + (long)(z & 7) * aI;
    const long boff = (long)(z >> 3) * bO + (long)(z & 7) * bI;
    const long coff = (long)(z >> 3) * cO + (long)(z & 7) * cI;

    const int tid = threadIdx.x;
    const int lane = tid & 31;
    const int wid = tid >> 5;
    const int wm = (wid >> 1) * 32;
    const int wn = (wid & 1) * (BN / 2);
    const int m0 = blockIdx.y * BM;
    const int n0 = blockIdx.x * BN;

    // A tile loader: 4 float4/thread; row = tid/8 + 32i, col4 = tid%8
    const int ar = tid >> 3, ac4 = tid & 7;
    // B tile loader
    constexpr int BFPR = BN / 4;             // float4 per B row
    constexpr int BRPP = 256 / BFPR;         // rows per pass
    constexpr int BIT = BK / BRPP;           // passes
    const int br = tid / BFPR, bc4 = tid % BFPR;

    const float* Ag = A + aoff + (long)(m0 + ar) * lda + ac4 * 4;
    const float* Bg = Bm + boff + (long)br * ldb + n0 + bc4 * 4;

    float acc[2][NI][4];
    #pragma unroll
    for (int mi = 0; mi < 2; mi++)
        #pragma unroll
        for (int ni = 0; ni < NI; ni++)
            #pragma unroll
            for (int j = 0; j < 4; j++) acc[mi][ni][j] = 0.0f;

    const int KT = K / BK;

    // prologue: stage 0
    {
        #pragma unroll
        for (int i = 0; i < 4; i++)
            cpasync16(&As[(ar + 32 * i) * AS + ac4 * 4], Ag + (long)(32 * i) * lda);
        #pragma unroll
        for (int i = 0; i < BIT; i++)
            cpasync16(&Bs[(br + BRPP * i) * BS + bc4 * 4], Bg + (long)(BRPP * i) * ldb);
        asm volatile("cp.async.commit_group;");
    }

    for (int kt = 0; kt < KT; kt++) {
        const int st = kt & 1;
        if (kt + 1 < KT) {
            const int sn = st ^ 1;
            const float* Agn = Ag + (kt + 1) * BK;
            const float* Bgn = Bg + (long)(kt + 1) * BK * ldb;
            #pragma unroll
            for (int i = 0; i < 4; i++)
                cpasync16(&As[sn * BM * AS + (ar + 32 * i) * AS + ac4 * 4],
                          Agn + (long)(32 * i) * lda);
            #pragma unroll
            for (int i = 0; i < BIT; i++)
                cpasync16(&Bs[sn * BK * BS + (br + BRPP * i) * BS + bc4 * 4],
                          Bgn + (long)(BRPP * i) * ldb);
            asm volatile("cp.async.commit_group;");
            asm volatile("cp.async.wait_group 1;");
        } else {
            asm volatile("cp.async.wait_group 0;");
        }
        __syncthreads();

        const float* A0 = As + st * BM * AS;
        const float* B0 = Bs + st * BK * BS;
        #pragma unroll
        for (int kk = 0; kk < BK; kk += 8) {
            uint32_t af[2][4];
            #pragma unroll
            for (int mi = 0; mi < 2; mi++) {
                const int r = wm + mi * 16 + (lane >> 2);
                const int c = kk + (lane & 3);
                af[mi][0] = __float_as_uint(A0[r * AS + c]);
                af[mi][1] = __float_as_uint(A0[(r + 8) * AS + c]);
                af[mi][2] = __float_as_uint(A0[r * AS + c + 4]);
                af[mi][3] = __float_as_uint(A0[(r + 8) * AS + c + 4]);
            }
            uint32_t bf[NI][2];
            #pragma unroll
            for (int ni = 0; ni < NI; ni++) {
                const int col = wn + ni * 8 + (lane >> 2);
                const int kr = kk + (lane & 3);
                bf[ni][0] = __float_as_uint(B0[kr * BS + col]);
                bf[ni][1] = __float_as_uint(B0[(kr + 4) * BS + col]);
            }
            #pragma unroll
            for (int mi = 0; mi < 2; mi++)
                #pragma unroll
                for (int ni = 0; ni < NI; ni++)
                    mma_tf32(acc[mi][ni], af[mi], bf[ni]);
        }
        __syncthreads();
    }

    // epilogue
    #pragma unroll
    for (int mi = 0; mi < 2; mi++) {
        const int r0 = m0 + wm + mi * 16 + (lane >> 2);
        #pragma unroll
        for (int ni = 0; ni < NI; ni++) {
            const int col = n0 + wn + ni * 8 + (lane & 3) * 2;
            #pragma unroll
            for (int half = 0; half < 2; half++) {
                const int r = r0 + half * 8;
                float v0 = acc[mi][ni][half * 2 + 0];
                float v1 = acc[mi][ni][half * 2 + 1];
                if (OP == 1) {
                    const float2 rs = *(const float2*)(resid + coff + (long)r * ldc + col);
                    v0 = rs.x + v0 + bias[col];
                    v1 = rs.y + v1 + bias[col + 1];
                } else if (OP == 2) {
                    v0 = gelu_exact(v0 + bias[col]);
                    v1 = gelu_exact(v1 + bias[col + 1]);
                }
                if (RND) { v0 = rtf32(v0); v1 = rtf32(v1); }
                float2 w2; w2.x = v0; w2.y = v1;
                *(float2*)(C + coff + (long)r * ldc + col) = w2;
            }
        }
    }
}

// ---------------- QK^T kernel (K=64, whole depth in smem) ----------------
// S[m,n] = scale * sum_k Q[m,k]*K[n,k], batched over z = b*8+h
__global__ __launch_bounds__(256) void qk_kernel(float scale) {
    constexpr int ASQ = 68, BSQ = 136;
    extern __shared__ float smem[];
    float* As = smem;              // [128][68]
    float* Bs = smem + 128 * ASQ;  // [64][136]

    const int z = blockIdx.z;
    const long qoff = (long)(z >> 3) * (Nc * Dc) + (long)(z & 7) * HDc;
    const size_t soff = (size_t)z * Nc * Nc;

    const int tid = threadIdx.x;
    const int lane = tid & 31;
    const int wid = tid >> 5;
    const int wm = (wid >> 1) * 32;
    const int wn = (wid & 1) * 64;
    const int m0 = blockIdx.y * 128;
    const int n0 = blockIdx.x * 128;

    // A = Q tile: 128 rows x 16 float4
    {
        const int r = tid >> 4, c4 = tid & 15;
        const float* Qg = g_q + qoff + (long)(m0 + r) * Dc + c4 * 4;
        #pragma unroll
        for (int i = 0; i < 8; i++)
            cpasync16(&As[(r + 16 * i) * ASQ + c4 * 4], Qg + (long)(16 * i) * Dc);
        asm volatile("cp.async.commit_group;");
    }
    // B = K^T tile: transpose-scatter (lanes map to distinct n -> conflict-free STS)
    {
        #pragma unroll
        for (int i = 0; i < 2; i++) {
            const int k4 = wid + 8 * i;
            #pragma unroll
            for (int j = 0; j < 4; j++) {
                const int n = lane + 32 * j;
                const float4 v = *(const float4*)(g_k + qoff + (long)(n0 + n) * Dc + k4 * 4);
                Bs[(4 * k4 + 0) * BSQ + n] = v.x;
                Bs[(4 * k4 + 1) * BSQ + n] = v.y;
                Bs[(4 * k4 + 2) * BSQ + n] = v.z;
                Bs[(4 * k4 + 3) * BSQ + n] = v.w;
            }
        }
    }
    asm volatile("cp.async.wait_group 0;");
    __syncthreads();

    float acc[2][8][4];
    #pragma unroll
    for (int mi = 0; mi < 2; mi++)
        #pragma unroll
        for (int ni = 0; ni < 8; ni++)
            #pragma unroll
            for (int j = 0; j < 4; j++) acc[mi][ni][j] = 0.0f;

    #pragma unroll
    for (int kk = 0; kk < 64; kk += 8) {
        uint32_t af[2][4];
        #pragma unroll
        for (int mi = 0; mi < 2; mi++) {
            const int r = wm + mi * 16 + (lane >> 2);
            const int c = kk + (lane & 3);
            af[mi][0] = __float_as_uint(As[r * ASQ + c]);
            af[mi][1] = __float_as_uint(As[(r + 8) * ASQ + c]);
            af[mi][2] = __float_as_uint(As[r * ASQ + c + 4]);
            af[mi][3] = __float_as_uint(As[(r + 8) * ASQ + c + 4]);
        }
        uint32_t bf[8][2];
        #pragma unroll
        for (int ni = 0; ni < 8; ni++) {
            const int col = wn + ni * 8 + (lane >> 2);
            const int kr = kk + (lane & 3);
            bf[ni][0] = __float_as_uint(Bs[kr * BSQ + col]);
            bf[ni][1] = __float_as_uint(Bs[(kr + 4) * BSQ + col]);
        }
        #pragma unroll
        for (int mi = 0; mi < 2; mi++)
            #pragma unroll
            for (int ni = 0; ni < 8; ni++)
                mma_tf32(acc[mi][ni], af[mi], bf[ni]);
    }

    #pragma unroll
    for (int mi = 0; mi < 2; mi++) {
        const int r0 = m0 + wm + mi * 16 + (lane >> 2);
        #pragma unroll
        for (int ni = 0; ni < 8; ni++) {
            const int col = n0 + wn + ni * 8 + (lane & 3) * 2;
            #pragma unroll
            for (int half = 0; half < 2; half++) {
                float2 w2;
                w2.x = acc[mi][ni][half * 2 + 0] * scale;
                w2.y = acc[mi][ni][half * 2 + 1] * scale;
                *(float2*)(g_s + soff + (size_t)(r0 + half * 8) * Nc + col) = w2;
            }
        }
    }
}

// ---------------- row softmax over S (2048 cols), output rounded ----------------
__global__ __launch_bounds__(256) void softmax_kernel() {
    const size_t row = blockIdx.x;
    float* p = g_s + row * Nc;
    const int t = threadIdx.x;
    float4 v0 = ((const float4*)p)[t * 2];
    float4 v1 = ((const float4*)p)[t * 2 + 1];
    float mx = fmaxf(fmaxf(fmaxf(v0.x, v0.y), fmaxf(v0.z, v0.w)),
                     fmaxf(fmaxf(v1.x, v1.y), fmaxf(v1.z, v1.w)));
    #pragma unroll
    for (int o = 16; o > 0; o >>= 1) mx = fmaxf(mx, __shfl_xor_sync(0xFFFFFFFFu, mx, o));
    __shared__ float sh[8];
    const int w = t >> 5;
    if ((t & 31) == 0) sh[w] = mx;
    __syncthreads();
    mx = fmaxf(fmaxf(fmaxf(sh[0], sh[1]), fmaxf(sh[2], sh[3])),
               fmaxf(fmaxf(sh[4], sh[5]), fmaxf(sh[6], sh[7])));
    v0.x = __expf(v0.x - mx); v0.y = __expf(v0.y - mx);
    v0.z = __expf(v0.z - mx); v0.w = __expf(v0.w - mx);
    v1.x = __expf(v1.x - mx); v1.y = __expf(v1.y - mx);
    v1.z = __expf(v1.z - mx); v1.w = __expf(v1.w - mx);
    float s = (v0.x + v0.y + v0.z + v0.w) + (v1.x + v1.y + v1.z + v1.w);
    #pragma unroll
    for (int o = 16; o > 0; o >>= 1) s += __shfl_xor_sync(0xFFFFFFFFu, s, o);
    __shared__ float sh2[8];
    if ((t & 31) == 0) sh2[w] = s;
    __syncthreads();
    s = (sh2[0] + sh2[1] + sh2[2] + sh2[3]) + (sh2[4] + sh2[5] + sh2[6] + sh2[7]);
    const float inv = 1.0f / s;
    float4 r0, r1;
    r0.x = rtf32(v0.x * inv); r0.y = rtf32(v0.y * inv);
    r0.z = rtf32(v0.z * inv); r0.w = rtf32(v0.w * inv);
    r1.x = rtf32(v1.x * inv); r1.y = rtf32(v1.y * inv);
    r1.z = rtf32(v1.z * inv); r1.w = rtf32(v1.w * inv);
    ((float4*)p)[t * 2] = r0;
    ((float4*)p)[t * 2 + 1] = r1;
}

// ---------------- driver ----------------
extern "C" void kernel_launch(void* const* d_in, const int* in_sizes, int n_in,
                              void* d_out, int out_size) {
    const float* x    = (const float*)d_in[0];
    const float* Wq   = (const float*)d_in[1];
    const float* Wk   = (const float*)d_in[2];
    const float* Wv   = (const float*)d_in[3];
    const float* Wo   = (const float*)d_in[4];
    const float* bo   = (const float*)d_in[5];
    const float* ln1g = (const float*)d_in[6];
    const float* ln1b = (const float*)d_in[7];
    const float* W1   = (const float*)d_in[8];
    const float* b1   = (const float*)d_in[9];
    const float* W2   = (const float*)d_in[10];
    const float* b2   = (const float*)d_in[11];
    const float* ln2g = (const float*)d_in[12];
    const float* ln2b = (const float*)d_in[13];
    float* h = (float*)d_out;

    float *py, *pq, *pk, *pv, *po, *pt, *ps, *pw;
    cudaGetSymbolAddress((void**)&py, g_y);
    cudaGetSymbolAddress((void**)&pq, g_q);
    cudaGetSymbolAddress((void**)&pk, g_k);
    cudaGetSymbolAddress((void**)&pv, g_v);
    cudaGetSymbolAddress((void**)&po, g_o);
    cudaGetSymbolAddress((void**)&pt, g_t);
    cudaGetSymbolAddress((void**)&ps, g_s);
    cudaGetSymbolAddress((void**)&pw, g_wr);

    // dynamic smem budgets
    const int smemProj = (2 * 128 * 36 + 2 * 32 * 136) * 4;  // 71680
    const int smemPV   = (2 * 128 * 36 + 2 * 32 * 72) * 4;   // 55296
    const int smemQK   = (128 * 68 + 64 * 136) * 4;          // 69632
    cudaFuncSetAttribute(gemm_pipe<128, 0, 1>, cudaFuncAttributeMaxDynamicSharedMemorySize, smemProj);
    cudaFuncSetAttribute(gemm_pipe<128, 1, 0>, cudaFuncAttributeMaxDynamicSharedMemorySize, smemProj);
    cudaFuncSetAttribute(gemm_pipe<128, 2, 1>, cudaFuncAttributeMaxDynamicSharedMemorySize, smemProj);
    cudaFuncSetAttribute(gemm_pipe<64, 0, 1>,  cudaFuncAttributeMaxDynamicSharedMemorySize, smemPV);
    cudaFuncSetAttribute(qk_kernel, cudaFuncAttributeMaxDynamicSharedMemorySize, smemQK);

    cudaMemcpyAsync(h, x, sizeof(float) * (size_t)Mrows * Dc, cudaMemcpyDeviceToDevice);

    // round all weights to tf32 grid once
    const int WSZ = Lc * Dc * Dc;  // 1M floats per weight tensor
    round_kernel<<<WSZ / 1024, 256>>>(Wq, pw + 0L * WSZ);
    round_kernel<<<WSZ / 1024, 256>>>(Wk, pw + 1L * WSZ);
    round_kernel<<<WSZ / 1024, 256>>>(Wv, pw + 2L * WSZ);
    round_kernel<<<WSZ / 1024, 256>>>(Wo, pw + 3L * WSZ);
    round_kernel<<<WSZ / 1024, 256>>>(W1, pw + 4L * WSZ);
    round_kernel<<<WSZ / 1024, 256>>>(W2, pw + 5L * WSZ);

    const float scale = 0.044194173824159216f;  // 512^-0.5
    const dim3 gProj(Dc / 128, Mrows / 128, 1);       // (4, 64)
    const dim3 gQK(Nc / 128, Nc / 128, Bc * Hc);      // (16, 16, 32)
    const dim3 gPV(1, Nc / 128, Bc * Hc);             // (1, 16, 32)
    const long NN = (long)Nc * Nc;
    const long BD = (long)Nc * Dc;

    for (int l = 0; l < Lc; l++) {
        const float* wq = pw + 0L * WSZ + (long)l * Dc * Dc;
        const float* wk = pw + 1L * WSZ + (long)l * Dc * Dc;
        const float* wv = pw + 2L * WSZ + (long)l * Dc * Dc;
        const float* wo = pw + 3L * WSZ + (long)l * Dc * Dc;
        const float* w1 = pw + 4L * WSZ + (long)l * Dc * Dc;
        const float* w2 = pw + 5L * WSZ + (long)l * Dc * Dc;

        ln_kernel<<<Mrows, 128>>>(h, ln1g + l * Dc, ln1b + l * Dc, py);
        gemm_pipe<128, 0, 1><<<gProj, 256, smemProj>>>(py, Dc, wq, Dc, pq, Dc, Dc,
                                                       nullptr, nullptr, 0, 0, 0, 0, 0, 0);
        gemm_pipe<128, 0, 1><<<gProj, 256, smemProj>>>(py, Dc, wk, Dc, pk, Dc, Dc,
                                                       nullptr, nullptr, 0, 0, 0, 0, 0, 0);
        gemm_pipe<128, 0, 1><<<gProj, 256, smemProj>>>(py, Dc, wv, Dc, pv, Dc, Dc,
                                                       nullptr, nullptr, 0, 0, 0, 0, 0, 0);
        qk_kernel<<<gQK, 256, smemQK>>>(scale);
        softmax_kernel<<<Bc * Hc * Nc, 256>>>();
        gemm_pipe<64, 0, 1><<<gPV, 256, smemPV>>>(ps, Nc, pv, Dc, po, Dc, Nc,
                                                  nullptr, nullptr,
                                                  8 * NN, NN, BD, HDc, BD, HDc);
        gemm_pipe<128, 1, 0><<<gProj, 256, smemProj>>>(po, Dc, wo, Dc, h, Dc, Dc,
                                                       bo + l * Dc, h, 0, 0, 0, 0, 0, 0);
        ln_kernel<<<Mrows, 128>>>(h, ln2g + l * Dc, ln2b + l * Dc, py);
        gemm_pipe<128, 2, 1><<<gProj, 256, smemProj>>>(py, Dc, w1, Dc, pt, Dc, Dc,
                                                       b1 + l * Dc, nullptr, 0, 0, 0, 0, 0, 0);
        gemm_pipe<128, 1, 0><<<gProj, 256, smemProj>>>(pt, Dc, w2, Dc, h, Dc, Dc,
                                                       b2 + l * Dc, h, 0, 0, 0, 0, 0, 0);
    }
}

// round 3
// speedup vs baseline: 4.4794x; 1.5344x over previous
#include <cuda_runtime.h>
#include <math.h>
#include <stdint.h>

#define Lc 4
#define Bc 4
#define Nc 2048
#define Dc 512
#define Hc 8
#define HDc 64
#define Mrows (Bc*Nc)   // 8192

// ---------------- scratch ----------------
__device__ float g_y[Mrows*Dc];
__device__ float g_q[Mrows*Dc];
__device__ float g_k[Mrows*Dc];
__device__ float g_v[Mrows*Dc];
__device__ float g_o[Mrows*Dc];
__device__ float g_t[Mrows*Dc];
__device__ float g_wr[6*Lc*Dc*Dc];                // tf32-rounded weights (25MB)

__device__ __forceinline__ float rtf32(float x) {
    uint32_t u;
    asm("cvt.rna.tf32.f32 %0, %1;" : "=r"(u) : "f"(x));
    return __uint_as_float(u);
}
__device__ __forceinline__ float gelu_exact(float x) {
    return 0.5f * x * (1.0f + erff(x * 0.70710678118654752f));
}
__device__ __forceinline__ void cpasync16(void* sdst, const void* gsrc) {
    uint32_t s = (uint32_t)__cvta_generic_to_shared(sdst);
    asm volatile("cp.async.cg.shared.global [%0], [%1], 16;" :: "r"(s), "l"(gsrc));
}
__device__ __forceinline__ void mma_tf32(float* d, const uint32_t* a, const uint32_t* b) {
    asm volatile("mma.sync.aligned.m16n8k8.row.col.f32.tf32.tf32.f32 "
                 "{%0,%1,%2,%3}, {%4,%5,%6,%7}, {%8,%9}, {%0,%1,%2,%3};"
                 : "+f"(d[0]), "+f"(d[1]), "+f"(d[2]), "+f"(d[3])
                 : "r"(a[0]), "r"(a[1]), "r"(a[2]), "r"(a[3]), "r"(b[0]), "r"(b[1]));
}

// ---------------- weight rounding (once per call) ----------------
__global__ __launch_bounds__(256) void round_kernel(const float* __restrict__ in,
                                                    float* __restrict__ out) {
    const int i = blockIdx.x * 256 + threadIdx.x;
    const float4 v = ((const float4*)in)[i];
    float4 r;
    r.x = rtf32(v.x); r.y = rtf32(v.y); r.z = rtf32(v.z); r.w = rtf32(v.w);
    ((float4*)out)[i] = r;
}

// ---------------- LayerNorm (output rounded to tf32 grid) ----------------
__global__ __launch_bounds__(128) void ln_kernel(const float* __restrict__ hin,
                                                 const float* __restrict__ gg,
                                                 const float* __restrict__ bb,
                                                 float* __restrict__ y) {
    const int row = blockIdx.x;
    const int t = threadIdx.x;
    const float4 v = ((const float4*)(hin + (size_t)row * Dc))[t];
    float s  = v.x + v.y + v.z + v.w;
    float ss = v.x*v.x + v.y*v.y + v.z*v.z + v.w*v.w;
    #pragma unroll
    for (int o = 16; o > 0; o >>= 1) {
        s  += __shfl_xor_sync(0xFFFFFFFFu, s, o);
        ss += __shfl_xor_sync(0xFFFFFFFFu, ss, o);
    }
    __shared__ float sh[8];
    const int w = t >> 5;
    if ((t & 31) == 0) { sh[w] = s; sh[4 + w] = ss; }
    __syncthreads();
    const float st  = sh[0] + sh[1] + sh[2] + sh[3];
    const float sst = sh[4] + sh[5] + sh[6] + sh[7];
    const float mu  = st * (1.0f / Dc);
    const float var = sst * (1.0f / Dc) - mu * mu;
    const float inv = rsqrtf(var + 1e-5f);
    const float4 g4 = ((const float4*)gg)[t];
    const float4 b4 = ((const float4*)bb)[t];
    float4 r;
    r.x = rtf32((v.x - mu) * inv * g4.x + b4.x);
    r.y = rtf32((v.y - mu) * inv * g4.y + b4.y);
    r.z = rtf32((v.z - mu) * inv * g4.z + b4.z);
    r.w = rtf32((v.w - mu) * inv * g4.w + b4.w);
    ((float4*)(y + (size_t)row * Dc))[t] = r;
}

// ---------------- pipelined tf32 MMA GEMM (projections / FF) ----------------
// OP 0: C = acc ; OP 1: C = resid + acc + bias ; OP 2: C = gelu(acc + bias)
template <int BN, int OP, int RND>
__global__ __launch_bounds__(256)
void gemm_pipe(const float* __restrict__ A, int lda,
               const float* __restrict__ Bm, int ldb,
               float* __restrict__ C, int ldc, int K,
               const float* __restrict__ bias, const float* __restrict__ resid) {
    constexpr int BM = 128, BK = 32;
    constexpr int AS = BK + 4;     // 36
    constexpr int BS = BN + 8;
    constexpr int NI = BN / 16;
    extern __shared__ float smem[];
    float* As = smem;                        // [2][BM][AS]
    float* Bs = smem + 2 * BM * AS;          // [2][BK][BS]

    const int tid = threadIdx.x;
    const int lane = tid & 31;
    const int wid = tid >> 5;
    const int wm = (wid >> 1) * 32;
    const int wn = (wid & 1) * (BN / 2);
    const int m0 = blockIdx.y * BM;
    const int n0 = blockIdx.x * BN;

    const int ar = tid >> 3, ac4 = tid & 7;
    constexpr int BFPR = BN / 4;
    constexpr int BRPP = 256 / BFPR;
    constexpr int BIT = BK / BRPP;
    const int br = tid / BFPR, bc4 = tid % BFPR;

    const float* Ag = A + (long)(m0 + ar) * lda + ac4 * 4;
    const float* Bg = Bm + (long)br * ldb + n0 + bc4 * 4;

    float acc[2][NI][4];
    #pragma unroll
    for (int mi = 0; mi < 2; mi++)
        #pragma unroll
        for (int ni = 0; ni < NI; ni++)
            #pragma unroll
            for (int j = 0; j < 4; j++) acc[mi][ni][j] = 0.0f;

    const int KT = K / BK;
    {
        #pragma unroll
        for (int i = 0; i < 4; i++)
            cpasync16(&As[(ar + 32 * i) * AS + ac4 * 4], Ag + (long)(32 * i) * lda);
        #pragma unroll
        for (int i = 0; i < BIT; i++)
            cpasync16(&Bs[(br + BRPP * i) * BS + bc4 * 4], Bg + (long)(BRPP * i) * ldb);
        asm volatile("cp.async.commit_group;");
    }

    for (int kt = 0; kt < KT; kt++) {
        const int st = kt & 1;
        if (kt + 1 < KT) {
            const int sn = st ^ 1;
            const float* Agn = Ag + (kt + 1) * BK;
            const float* Bgn = Bg + (long)(kt + 1) * BK * ldb;
            #pragma unroll
            for (int i = 0; i < 4; i++)
                cpasync16(&As[sn * BM * AS + (ar + 32 * i) * AS + ac4 * 4],
                          Agn + (long)(32 * i) * lda);
            #pragma unroll
            for (int i = 0; i < BIT; i++)
                cpasync16(&Bs[sn * BK * BS + (br + BRPP * i) * BS + bc4 * 4],
                          Bgn + (long)(BRPP * i) * ldb);
            asm volatile("cp.async.commit_group;");
            asm volatile("cp.async.wait_group 1;");
        } else {
            asm volatile("cp.async.wait_group 0;");
        }
        __syncthreads();

        const float* A0 = As + st * BM * AS;
        const float* B0 = Bs + st * BK * BS;
        #pragma unroll
        for (int kk = 0; kk < BK; kk += 8) {
            uint32_t af[2][4];
            #pragma unroll
            for (int mi = 0; mi < 2; mi++) {
                const int r = wm + mi * 16 + (lane >> 2);
                const int c = kk + (lane & 3);
                af[mi][0] = __float_as_uint(A0[r * AS + c]);
                af[mi][1] = __float_as_uint(A0[(r + 8) * AS + c]);
                af[mi][2] = __float_as_uint(A0[r * AS + c + 4]);
                af[mi][3] = __float_as_uint(A0[(r + 8) * AS + c + 4]);
            }
            uint32_t bf[NI][2];
            #pragma unroll
            for (int ni = 0; ni < NI; ni++) {
                const int col = wn + ni * 8 + (lane >> 2);
                const int kr = kk + (lane & 3);
                bf[ni][0] = __float_as_uint(B0[kr * BS + col]);
                bf[ni][1] = __float_as_uint(B0[(kr + 4) * BS + col]);
            }
            #pragma unroll
            for (int mi = 0; mi < 2; mi++)
                #pragma unroll
                for (int ni = 0; ni < NI; ni++)
                    mma_tf32(acc[mi][ni], af[mi], bf[ni]);
        }
        __syncthreads();
    }

    #pragma unroll
    for (int mi = 0; mi < 2; mi++) {
        const int r0 = m0 + wm + mi * 16 + (lane >> 2);
        #pragma unroll
        for (int ni = 0; ni < NI; ni++) {
            const int col = n0 + wn + ni * 8 + (lane & 3) * 2;
            #pragma unroll
            for (int half = 0; half < 2; half++) {
                const int r = r0 + half * 8;
                float v0 = acc[mi][ni][half * 2 + 0];
                float v1 = acc[mi][ni][half * 2 + 1];
                if (OP == 1) {
                    const float2 rs = *(const float2*)(resid + (long)r * ldc + col);
                    v0 = rs.x + v0 + bias[col];
                    v1 = rs.y + v1 + bias[col + 1];
                } else if (OP == 2) {
                    v0 = gelu_exact(v0 + bias[col]);
                    v1 = gelu_exact(v1 + bias[col + 1]);
                }
                if (RND) { v0 = rtf32(v0); v1 = rtf32(v1); }
                float2 w2; w2.x = v0; w2.y = v1;
                *(float2*)(C + (long)r * ldc + col) = w2;
            }
        }
    }
}

// ---------------- fused flash attention (tf32 MMA, no score matrix) ----------------
// grid (Nc/128, Hc, Bc), 256 thr. Warp w owns rows [w*16, w*16+16) of the Q tile.
// S fragments are reused as PV's A operand via token permutation tau(k)=2k / 2(k-4)+1
// applied to V's row index at LDS time.
__global__ __launch_bounds__(256, 2) void fattn_kernel() {
    constexpr int KS = 68;
    extern __shared__ float smem[];
    float* Qs  = smem;                  // [128][68]
    float* Ksm = smem + 128 * KS;       // [2][64][68]
    float* Vsm = Ksm + 2 * 64 * KS;     // [2][64][68]

    const int qt = blockIdx.x, hh = blockIdx.y, bb = blockIdx.z;
    const int tid = threadIdx.x, lane = tid & 31, wid = tid >> 5;
    const long base = (long)bb * Nc * Dc + hh * HDc;
    const float scale = 0.044194173824159216f;  // 512^-0.5

    // stage Q tile + K/V tile 0
    {
        const int r = tid >> 4, c4 = tid & 15;
        #pragma unroll
        for (int i = 0; i < 8; i++)
            cpasync16(&Qs[(r + 16 * i) * KS + c4 * 4],
                      g_q + base + (long)(qt * 128 + r + 16 * i) * Dc + c4 * 4);
    }
    {
        const int r = tid >> 2;
        #pragma unroll
        for (int i = 0; i < 4; i++) {
            const int c4 = (tid & 3) + 4 * i;
            cpasync16(&Ksm[r * KS + c4 * 4], g_k + base + (long)r * Dc + c4 * 4);
            cpasync16(&Vsm[r * KS + c4 * 4], g_v + base + (long)r * Dc + c4 * 4);
        }
    }
    asm volatile("cp.async.commit_group;");
    asm volatile("cp.async.wait_group 0;");
    __syncthreads();

    // Q fragments: 8 k-atoms
    uint32_t qf[8][4];
    {
        const int r0 = wid * 16 + (lane >> 2);
        #pragma unroll
        for (int k0 = 0; k0 < 8; k0++) {
            const int c = k0 * 8 + (lane & 3);
            qf[k0][0] = __float_as_uint(Qs[r0 * KS + c]);
            qf[k0][1] = __float_as_uint(Qs[(r0 + 8) * KS + c]);
            qf[k0][2] = __float_as_uint(Qs[r0 * KS + c + 4]);
            qf[k0][3] = __float_as_uint(Qs[(r0 + 8) * KS + c + 4]);
        }
    }

    float o[8][4];
    #pragma unroll
    for (int d = 0; d < 8; d++)
        #pragma unroll
        for (int j = 0; j < 4; j++) o[d][j] = 0.0f;
    float m0 = -1e30f, m1 = -1e30f, l0 = 0.0f, l1 = 0.0f;

    for (int kt = 0; kt < Nc / 64; kt++) {
        const int st = kt & 1;
        if (kt + 1 < Nc / 64) {
            const int sn = st ^ 1;
            const int r = tid >> 2;
            const long gb = base + (long)((kt + 1) * 64 + r) * Dc;
            #pragma unroll
            for (int i = 0; i < 4; i++) {
                const int c4 = (tid & 3) + 4 * i;
                cpasync16(&Ksm[sn * 64 * KS + r * KS + c4 * 4], g_k + gb + c4 * 4);
                cpasync16(&Vsm[sn * 64 * KS + r * KS + c4 * 4], g_v + gb + c4 * 4);
            }
            asm volatile("cp.async.commit_group;");
            asm volatile("cp.async.wait_group 1;");
        } else {
            asm volatile("cp.async.wait_group 0;");
        }
        __syncthreads();

        const float* K0 = Ksm + st * 64 * KS;
        const float* V0 = Vsm + st * 64 * KS;

        // S = Q @ K^T  (K natural layout == col-major B)
        float sc[8][4];
        #pragma unroll
        for (int j = 0; j < 8; j++)
            #pragma unroll
            for (int i = 0; i < 4; i++) sc[j][i] = 0.0f;
        #pragma unroll
        for (int j = 0; j < 8; j++) {
            const int row = j * 8 + (lane >> 2);
            #pragma unroll
            for (int k0 = 0; k0 < 8; k0++) {
                uint32_t b[2];
                const int col = k0 * 8 + (lane & 3);
                b[0] = __float_as_uint(K0[row * KS + col]);
                b[1] = __float_as_uint(K0[row * KS + col + 4]);
                mma_tf32(sc[j], qf[k0], b);
            }
        }

        // online softmax (rows r0 = lane>>2 and r0+8; 4 lanes per row)
        float tm0 = -1e30f, tm1 = -1e30f;
        #pragma unroll
        for (int j = 0; j < 8; j++) {
            sc[j][0] *= scale; sc[j][1] *= scale;
            sc[j][2] *= scale; sc[j][3] *= scale;
            tm0 = fmaxf(tm0, fmaxf(sc[j][0], sc[j][1]));
            tm1 = fmaxf(tm1, fmaxf(sc[j][2], sc[j][3]));
        }
        tm0 = fmaxf(tm0, __shfl_xor_sync(0xFFFFFFFFu, tm0, 1));
        tm0 = fmaxf(tm0, __shfl_xor_sync(0xFFFFFFFFu, tm0, 2));
        tm1 = fmaxf(tm1, __shfl_xor_sync(0xFFFFFFFFu, tm1, 1));
        tm1 = fmaxf(tm1, __shfl_xor_sync(0xFFFFFFFFu, tm1, 2));
        const float nm0 = fmaxf(m0, tm0), nm1 = fmaxf(m1, tm1);
        const float c0 = __expf(m0 - nm0), c1 = __expf(m1 - nm1);
        m0 = nm0; m1 = nm1; l0 *= c0; l1 *= c1;
        #pragma unroll
        for (int j = 0; j < 8; j++) {
            const float p0 = __expf(sc[j][0] - m0);
            const float p1 = __expf(sc[j][1] - m0);
            const float p2 = __expf(sc[j][2] - m1);
            const float p3 = __expf(sc[j][3] - m1);
            l0 += p0 + p1; l1 += p2 + p3;
            sc[j][0] = rtf32(p0); sc[j][1] = rtf32(p1);
            sc[j][2] = rtf32(p2); sc[j][3] = rtf32(p3);
        }
        #pragma unroll
        for (int d = 0; d < 8; d++) {
            o[d][0] *= c0; o[d][1] *= c0; o[d][2] *= c1; o[d][3] *= c1;
        }

        // O += P @ V  (acc fragment reused as A via tau permutation on V rows)
        #pragma unroll
        for (int j = 0; j < 8; j++) {
            uint32_t a[4];
            a[0] = __float_as_uint(sc[j][0]);
            a[1] = __float_as_uint(sc[j][2]);
            a[2] = __float_as_uint(sc[j][1]);
            a[3] = __float_as_uint(sc[j][3]);
            const int vr = j * 8 + 2 * (lane & 3);
            #pragma unroll
            for (int d = 0; d < 8; d++) {
                uint32_t b[2];
                const int col = d * 8 + (lane >> 2);
                b[0] = __float_as_uint(V0[vr * KS + col]);
                b[1] = __float_as_uint(V0[(vr + 1) * KS + col]);
                mma_tf32(o[d], a, b);
            }
        }
        __syncthreads();
    }

    l0 += __shfl_xor_sync(0xFFFFFFFFu, l0, 1);
    l0 += __shfl_xor_sync(0xFFFFFFFFu, l0, 2);
    l1 += __shfl_xor_sync(0xFFFFFFFFu, l1, 1);
    l1 += __shfl_xor_sync(0xFFFFFFFFu, l1, 2);
    const float i0 = 1.0f / l0, i1 = 1.0f / l1;

    const int r0 = qt * 128 + wid * 16 + (lane >> 2);
    float* op0 = g_o + base + (long)r0 * Dc;
    float* op1 = op0 + 8 * Dc;
    #pragma unroll
    for (int d = 0; d < 8; d++) {
        const int col = d * 8 + 2 * (lane & 3);
        float2 w0, w1;
        w0.x = rtf32(o[d][0] * i0); w0.y = rtf32(o[d][1] * i0);
        w1.x = rtf32(o[d][2] * i1); w1.y = rtf32(o[d][3] * i1);
        *(float2*)(op0 + col) = w0;
        *(float2*)(op1 + col) = w1;
    }
}

// ---------------- driver ----------------
extern "C" void kernel_launch(void* const* d_in, const int* in_sizes, int n_in,
                              void* d_out, int out_size) {
    const float* x    = (const float*)d_in[0];
    const float* Wq   = (const float*)d_in[1];
    const float* Wk   = (const float*)d_in[2];
    const float* Wv   = (const float*)d_in[3];
    const float* Wo   = (const float*)d_in[4];
    const float* bo   = (const float*)d_in[5];
    const float* ln1g = (const float*)d_in[6];
    const float* ln1b = (const float*)d_in[7];
    const float* W1   = (const float*)d_in[8];
    const float* b1   = (const float*)d_in[9];
    const float* W2   = (const float*)d_in[10];
    const float* b2   = (const float*)d_in[11];
    const float* ln2g = (const float*)d_in[12];
    const float* ln2b = (const float*)d_in[13];
    float* h = (float*)d_out;

    float *py, *pq, *pk, *pv, *po, *pt, *pw;
    cudaGetSymbolAddress((void**)&py, g_y);
    cudaGetSymbolAddress((void**)&pq, g_q);
    cudaGetSymbolAddress((void**)&pk, g_k);
    cudaGetSymbolAddress((void**)&pv, g_v);
    cudaGetSymbolAddress((void**)&po, g_o);
    cudaGetSymbolAddress((void**)&pt, g_t);
    cudaGetSymbolAddress((void**)&pw, g_wr);

    const int smemProj = (2 * 128 * 36 + 2 * 32 * 136) * 4;  // 71680
    const int smemAttn = (128 * 68 + 4 * 64 * 68) * 4;       // 104448
    cudaFuncSetAttribute(gemm_pipe<128, 0, 1>, cudaFuncAttributeMaxDynamicSharedMemorySize, smemProj);
    cudaFuncSetAttribute(gemm_pipe<128, 1, 0>, cudaFuncAttributeMaxDynamicSharedMemorySize, smemProj);
    cudaFuncSetAttribute(gemm_pipe<128, 2, 1>, cudaFuncAttributeMaxDynamicSharedMemorySize, smemProj);
    cudaFuncSetAttribute(fattn_kernel, cudaFuncAttributeMaxDynamicSharedMemorySize, smemAttn);

    cudaMemcpyAsync(h, x, sizeof(float) * (size_t)Mrows * Dc, cudaMemcpyDeviceToDevice);

    const int WSZ = Lc * Dc * Dc;
    round_kernel<<<WSZ / 1024, 256>>>(Wq, pw + 0L * WSZ);
    round_kernel<<<WSZ / 1024, 256>>>(Wk, pw + 1L * WSZ);
    round_kernel<<<WSZ / 1024, 256>>>(Wv, pw + 2L * WSZ);
    round_kernel<<<WSZ / 1024, 256>>>(Wo, pw + 3L * WSZ);
    round_kernel<<<WSZ / 1024, 256>>>(W1, pw + 4L * WSZ);
    round_kernel<<<WSZ / 1024, 256>>>(W2, pw + 5L * WSZ);

    const dim3 gProj(Dc / 128, Mrows / 128, 1);     // (4, 64)
    const dim3 gAttn(Nc / 128, Hc, Bc);             // (16, 8, 4)

    for (int l = 0; l < Lc; l++) {
        const float* wq = pw + 0L * WSZ + (long)l * Dc * Dc;
        const float* wk = pw + 1L * WSZ + (long)l * Dc * Dc;
        const float* wv = pw + 2L * WSZ + (long)l * Dc * Dc;
        const float* wo = pw + 3L * WSZ + (long)l * Dc * Dc;
        const float* w1 = pw + 4L * WSZ + (long)l * Dc * Dc;
        const float* w2 = pw + 5L * WSZ + (long)l * Dc * Dc;

        ln_kernel<<<Mrows, 128>>>(h, ln1g + l * Dc, ln1b + l * Dc, py);
        gemm_pipe<128, 0, 1><<<gProj, 256, smemProj>>>(py, Dc, wq, Dc, pq, Dc, Dc, nullptr, nullptr);
        gemm_pipe<128, 0, 1><<<gProj, 256, smemProj>>>(py, Dc, wk, Dc, pk, Dc, Dc, nullptr, nullptr);
        gemm_pipe<128, 0, 1><<<gProj, 256, smemProj>>>(py, Dc, wv, Dc, pv, Dc, Dc, nullptr, nullptr);
        fattn_kernel<<<gAttn, 256, smemAttn>>>();
        gemm_pipe<128, 1, 0><<<gProj, 256, smemProj>>>(po, Dc, wo, Dc, h, Dc, Dc, bo + l * Dc, h);
        ln_kernel<<<Mrows, 128>>>(h, ln2g + l * Dc, ln2b + l * Dc, py);
        gemm_pipe<128, 2, 1><<<gProj, 256, smemProj>>>(py, Dc, w1, Dc, pt, Dc, Dc, b1 + l * Dc, nullptr);
        gemm_pipe<128, 1, 0><<<gProj, 256, smemProj>>>(pt, Dc, w2, Dc, h, Dc, Dc, b2 + l * Dc, h);
    }
}

// round 5
// speedup vs baseline: 6.1396x; 1.3706x over previous
#include <cuda_runtime.h>
#include <cuda_bf16.h>
#include <math.h>
#include <stdint.h>

#define Lc 4
#define Bc 4
#define Nc 2048
#define Dc 512
#define Hc 8
#define HDc 64
#define Mrows (Bc*Nc)   // 8192

// ---------------- scratch ----------------
__device__ float g_y[Mrows*Dc];
__device__ float g_o[Mrows*Dc];
__device__ float g_t[Mrows*Dc];
__device__ float g_wr[6*Lc*Dc*Dc];                 // tf32-rounded weights
__device__ __nv_bfloat16 g_qb[Mrows*Dc];           // Q (pre-scaled, bf16)
__device__ __nv_bfloat16 g_kb[Mrows*Dc];           // K bf16
__device__ __nv_bfloat16 g_vt[Mrows*Dc];           // V bf16, per-(b,h) transposed [64][2048]

__device__ __forceinline__ float rtf32(float x) {
    uint32_t u;
    asm("cvt.rna.tf32.f32 %0, %1;" : "=r"(u) : "f"(x));
    return __uint_as_float(u);
}
__device__ __forceinline__ float gelu_exact(float x) {
    return 0.5f * x * (1.0f + erff(x * 0.70710678118654752f));
}
__device__ __forceinline__ float ex2(float x) {
    float r;
    asm("ex2.approx.f32 %0, %1;" : "=f"(r) : "f"(x));
    return r;
}
__device__ __forceinline__ void cpasync16(void* sdst, const void* gsrc) {
    uint32_t s = (uint32_t)__cvta_generic_to_shared(sdst);
    asm volatile("cp.async.cg.shared.global [%0], [%1], 16;" :: "r"(s), "l"(gsrc));
}
__device__ __forceinline__ void mma_tf32(float* d, const uint32_t* a, const uint32_t* b) {
    asm volatile("mma.sync.aligned.m16n8k8.row.col.f32.tf32.tf32.f32 "
                 "{%0,%1,%2,%3}, {%4,%5,%6,%7}, {%8,%9}, {%0,%1,%2,%3};"
                 : "+f"(d[0]), "+f"(d[1]), "+f"(d[2]), "+f"(d[3])
                 : "r"(a[0]), "r"(a[1]), "r"(a[2]), "r"(a[3]), "r"(b[0]), "r"(b[1]));
}
__device__ __forceinline__ void mma_bf16(float* d, const uint32_t* a, const uint32_t* b) {
    asm volatile("mma.sync.aligned.m16n8k16.row.col.f32.bf16.bf16.f32 "
                 "{%0,%1,%2,%3}, {%4,%5,%6,%7}, {%8,%9}, {%0,%1,%2,%3};"
                 : "+f"(d[0]), "+f"(d[1]), "+f"(d[2]), "+f"(d[3])
                 : "r"(a[0]), "r"(a[1]), "r"(a[2]), "r"(a[3]), "r"(b[0]), "r"(b[1]));
}
__device__ __forceinline__ uint32_t packbf(float lo, float hi) {
    __nv_bfloat162 p = __floats2bfloat162_rn(lo, hi);  // .x = lo, .y = hi
    return *(uint32_t*)&p;
}

// ---------------- weight rounding ----------------
__global__ __launch_bounds__(256) void round_kernel(const float* __restrict__ in,
                                                    float* __restrict__ out) {
    const int i = blockIdx.x * 256 + threadIdx.x;
    const float4 v = ((const float4*)in)[i];
    float4 r;
    r.x = rtf32(v.x); r.y = rtf32(v.y); r.z = rtf32(v.z); r.w = rtf32(v.w);
    ((float4*)out)[i] = r;
}

// ---------------- LayerNorm (output rounded to tf32 grid) ----------------
__global__ __launch_bounds__(128) void ln_kernel(const float* __restrict__ hin,
                                                 const float* __restrict__ gg,
                                                 const float* __restrict__ bb,
                                                 float* __restrict__ y) {
    const int row = blockIdx.x;
    const int t = threadIdx.x;
    const float4 v = ((const float4*)(hin + (size_t)row * Dc))[t];
    float s  = v.x + v.y + v.z + v.w;
    float ss = v.x*v.x + v.y*v.y + v.z*v.z + v.w*v.w;
    #pragma unroll
    for (int o = 16; o > 0; o >>= 1) {
        s  += __shfl_xor_sync(0xFFFFFFFFu, s, o);
        ss += __shfl_xor_sync(0xFFFFFFFFu, ss, o);
    }
    __shared__ float sh[8];
    const int w = t >> 5;
    if ((t & 31) == 0) { sh[w] = s; sh[4 + w] = ss; }
    __syncthreads();
    const float st  = sh[0] + sh[1] + sh[2] + sh[3];
    const float sst = sh[4] + sh[5] + sh[6] + sh[7];
    const float mu  = st * (1.0f / Dc);
    const float var = sst * (1.0f / Dc) - mu * mu;
    const float inv = rsqrtf(var + 1e-5f);
    const float4 g4 = ((const float4*)gg)[t];
    const float4 b4 = ((const float4*)bb)[t];
    float4 r;
    r.x = rtf32((v.x - mu) * inv * g4.x + b4.x);
    r.y = rtf32((v.y - mu) * inv * g4.y + b4.y);
    r.z = rtf32((v.z - mu) * inv * g4.z + b4.z);
    r.w = rtf32((v.w - mu) * inv * g4.w + b4.w);
    ((float4*)(y + (size_t)row * Dc))[t] = r;
}

// ================= shared tf32 GEMM mainloop (BM=128, BN=128, BK=32) =================
// acc[2][8][4] per thread; 8 warps as 4x2; returns with accumulators filled.
struct GemmCtx {
    int lane, wid, wm, wn, m0, n0;
};
__device__ __forceinline__ void gemm_mainloop(const float* __restrict__ A, int lda,
                                              const float* __restrict__ Bm, int ldb,
                                              int K, float* smem, GemmCtx& cx,
                                              float acc[2][8][4]) {
    constexpr int BM = 128, BK = 32, BN = 128;
    constexpr int AS = BK + 4, BS = BN + 8;
    float* As = smem;
    float* Bs = smem + 2 * BM * AS;

    const int tid = threadIdx.x;
    cx.lane = tid & 31; cx.wid = tid >> 5;
    cx.wm = (cx.wid >> 1) * 32; cx.wn = (cx.wid & 1) * 64;
    cx.m0 = blockIdx.y * BM; cx.n0 = blockIdx.x * BN;

    const int ar = tid >> 3, ac4 = tid & 7;
    const int br = tid >> 5, bc4 = tid & 31;

    const float* Ag = A + (long)(cx.m0 + ar) * lda + ac4 * 4;
    const float* Bg = Bm + (long)br * ldb + cx.n0 + bc4 * 4;

    #pragma unroll
    for (int mi = 0; mi < 2; mi++)
        #pragma unroll
        for (int ni = 0; ni < 8; ni++)
            #pragma unroll
            for (int j = 0; j < 4; j++) acc[mi][ni][j] = 0.0f;

    const int KT = K / BK;
    {
        #pragma unroll
        for (int i = 0; i < 4; i++)
            cpasync16(&As[(ar + 32 * i) * AS + ac4 * 4], Ag + (long)(32 * i) * lda);
        #pragma unroll
        for (int i = 0; i < 4; i++)
            cpasync16(&Bs[(br + 8 * i) * BS + bc4 * 4], Bg + (long)(8 * i) * ldb);
        asm volatile("cp.async.commit_group;");
    }

    for (int kt = 0; kt < KT; kt++) {
        const int st = kt & 1;
        if (kt + 1 < KT) {
            const int sn = st ^ 1;
            const float* Agn = Ag + (kt + 1) * BK;
            const float* Bgn = Bg + (long)(kt + 1) * BK * ldb;
            #pragma unroll
            for (int i = 0; i < 4; i++)
                cpasync16(&As[sn * BM * AS + (ar + 32 * i) * AS + ac4 * 4],
                          Agn + (long)(32 * i) * lda);
            #pragma unroll
            for (int i = 0; i < 4; i++)
                cpasync16(&Bs[sn * BK * BS + (br + 8 * i) * BS + bc4 * 4],
                          Bgn + (long)(8 * i) * ldb);
            asm volatile("cp.async.commit_group;");
            asm volatile("cp.async.wait_group 1;");
        } else {
            asm volatile("cp.async.wait_group 0;");
        }
        __syncthreads();

        const float* A0 = As + st * BM * AS;
        const float* B0 = Bs + st * BK * BS;
        #pragma unroll
        for (int kk = 0; kk < BK; kk += 8) {
            uint32_t af[2][4];
            #pragma unroll
            for (int mi = 0; mi < 2; mi++) {
                const int r = cx.wm + mi * 16 + (cx.lane >> 2);
                const int c = kk + (cx.lane & 3);
                af[mi][0] = __float_as_uint(A0[r * AS + c]);
                af[mi][1] = __float_as_uint(A0[(r + 8) * AS + c]);
                af[mi][2] = __float_as_uint(A0[r * AS + c + 4]);
                af[mi][3] = __float_as_uint(A0[(r + 8) * AS + c + 4]);
            }
            uint32_t bf[8][2];
            #pragma unroll
            for (int ni = 0; ni < 8; ni++) {
                const int col = cx.wn + ni * 8 + (cx.lane >> 2);
                const int kr = kk + (cx.lane & 3);
                bf[ni][0] = __float_as_uint(B0[kr * BS + col]);
                bf[ni][1] = __float_as_uint(B0[(kr + 4) * BS + col]);
            }
            #pragma unroll
            for (int mi = 0; mi < 2; mi++)
                #pragma unroll
                for (int ni = 0; ni < 8; ni++)
                    mma_tf32(acc[mi][ni], af[mi], bf[ni]);
        }
        __syncthreads();
    }
}

// ---------------- generic GEMM with fp32 epilogue ----------------
// OP 0: C = acc ; OP 1: C = resid + acc + bias ; OP 2: C = gelu(acc + bias)
template <int OP, int RND>
__global__ __launch_bounds__(256)
void gemm_pipe(const float* __restrict__ A, const float* __restrict__ Bm,
               float* __restrict__ C,
               const float* __restrict__ bias, const float* __restrict__ resid) {
    extern __shared__ float smem[];
    GemmCtx cx;
    float acc[2][8][4];
    gemm_mainloop(A, Dc, Bm, Dc, Dc, smem, cx, acc);

    #pragma unroll
    for (int mi = 0; mi < 2; mi++) {
        const int r0 = cx.m0 + cx.wm + mi * 16 + (cx.lane >> 2);
        #pragma unroll
        for (int ni = 0; ni < 8; ni++) {
            const int col = cx.n0 + cx.wn + ni * 8 + (cx.lane & 3) * 2;
            #pragma unroll
            for (int half = 0; half < 2; half++) {
                const int r = r0 + half * 8;
                float v0 = acc[mi][ni][half * 2 + 0];
                float v1 = acc[mi][ni][half * 2 + 1];
                if (OP == 1) {
                    const float2 rs = *(const float2*)(resid + (long)r * Dc + col);
                    v0 = rs.x + v0 + bias[col];
                    v1 = rs.y + v1 + bias[col + 1];
                } else if (OP == 2) {
                    v0 = gelu_exact(v0 + bias[col]);
                    v1 = gelu_exact(v1 + bias[col + 1]);
                }
                if (RND) { v0 = rtf32(v0); v1 = rtf32(v1); }
                float2 w2; w2.x = v0; w2.y = v1;
                *(float2*)(C + (long)r * Dc + col) = w2;
            }
        }
    }
}

// ---------------- QKV GEMM: z selects weight + bf16 output layout ----------------
#define QSC 0.06376237f  /* 512^-0.5 * log2(e) */
__global__ __launch_bounds__(256)
void qkv_gemm(const float* __restrict__ A, const float* __restrict__ wq,
              const float* __restrict__ wk, const float* __restrict__ wv) {
    extern __shared__ float smem[];
    const int z = blockIdx.z;
    const float* W = (z == 0) ? wq : (z == 1) ? wk : wv;
    GemmCtx cx;
    float acc[2][8][4];
    gemm_mainloop(A, Dc, W, Dc, Dc, smem, cx, acc);

    #pragma unroll
    for (int mi = 0; mi < 2; mi++) {
        const int r0 = cx.m0 + cx.wm + mi * 16 + (cx.lane >> 2);
        #pragma unroll
        for (int ni = 0; ni < 8; ni++) {
            const int col = cx.n0 + cx.wn + ni * 8 + (cx.lane & 3) * 2;
            #pragma unroll
            for (int half = 0; half < 2; half++) {
                const int r = r0 + half * 8;
                float v0 = acc[mi][ni][half * 2 + 0];
                float v1 = acc[mi][ni][half * 2 + 1];
                if (z == 0) {
                    *(uint32_t*)(g_qb + (long)r * Dc + col) = packbf(v0 * QSC, v1 * QSC);
                } else if (z == 1) {
                    *(uint32_t*)(g_kb + (long)r * Dc + col) = packbf(v0, v1);
                } else {
                    const int bidx = r >> 11, tok = r & 2047;
                    const long hb = ((long)bidx * Hc + (col >> 6)) * (HDc * Nc);
                    g_vt[hb + (long)(col & 63) * Nc + tok] = __float2bfloat16(v0);
                    g_vt[hb + (long)((col + 1) & 63) * Nc + tok] = __float2bfloat16(v1);
                }
            }
        }
    }
}

// ---------------- bf16 fused flash attention ----------------
// grid (Nc/128, Hc, Bc), 256 thr, warp w owns Q rows [16w,16w+16).
__global__ __launch_bounds__(256, 2) void fattn_kernel() {
    constexpr int QS = 72;                 // bf16 elems per smem row (36 words)
    extern __shared__ __align__(16) char smraw[];
    __nv_bfloat16* Qs = (__nv_bfloat16*)smraw;      // [128][72]
    __nv_bfloat16* Ks = Qs + 128 * QS;              // [2][64][72]
    __nv_bfloat16* Vt = Ks + 2 * 64 * QS;           // [2][64][72] (dim-major)

    const int qt = blockIdx.x, hh = blockIdx.y, bb = blockIdx.z;
    const int tid = threadIdx.x, lane = tid & 31, wid = tid >> 5;
    const long kvbase = ((long)bb * Nc) * Dc + hh * HDc;       // into g_kb
    const long vtbase = ((long)bb * Hc + hh) * (HDc * Nc);     // into g_vt

    // stage Q tile + K/V tile 0
    #pragma unroll
    for (int i = 0; i < 4; i++) {
        const int idx = tid + 256 * i;
        const int r = idx >> 3, ch = idx & 7;
        cpasync16(&Qs[r * QS + ch * 8],
                  g_qb + kvbase + (long)(qt * 128 + r) * Dc + ch * 8);
    }
    #pragma unroll
    for (int i = 0; i < 2; i++) {
        const int idx = tid + 256 * i;
        const int r = idx >> 3, ch = idx & 7;
        cpasync16(&Ks[r * QS + ch * 8], g_kb + kvbase + (long)r * Dc + ch * 8);
        cpasync16(&Vt[r * QS + ch * 8], g_vt + vtbase + (long)r * Nc + ch * 8);
    }
    asm volatile("cp.async.commit_group;");
    asm volatile("cp.async.wait_group 0;");
    __syncthreads();

    // Q fragments: 4 k16-atoms x 4 regs (bf16 pairs)
    uint32_t qf[4][4];
    {
        const uint32_t* Qw = (const uint32_t*)Qs;
        const int r0 = wid * 16 + (lane >> 2);
        #pragma unroll
        for (int ka = 0; ka < 4; ka++) {
            const int c = ka * 8 + (lane & 3);
            qf[ka][0] = Qw[r0 * 36 + c];
            qf[ka][1] = Qw[(r0 + 8) * 36 + c];
            qf[ka][2] = Qw[r0 * 36 + c + 4];
            qf[ka][3] = Qw[(r0 + 8) * 36 + c + 4];
        }
    }

    float o[8][4];
    #pragma unroll
    for (int d = 0; d < 8; d++)
        #pragma unroll
        for (int j = 0; j < 4; j++) o[d][j] = 0.0f;
    float m0 = -1e30f, m1 = -1e30f, l0 = 0.0f, l1 = 0.0f;

    for (int kt = 0; kt < Nc / 64; kt++) {
        const int st = kt & 1;
        if (kt + 1 < Nc / 64) {
            const int sn = st ^ 1;
            #pragma unroll
            for (int i = 0; i < 2; i++) {
                const int idx = tid + 256 * i;
                const int r = idx >> 3, ch = idx & 7;
                cpasync16(&Ks[sn * 64 * QS + r * QS + ch * 8],
                          g_kb + kvbase + (long)((kt + 1) * 64 + r) * Dc + ch * 8);
                cpasync16(&Vt[sn * 64 * QS + r * QS + ch * 8],
                          g_vt + vtbase + (long)r * Nc + (kt + 1) * 64 + ch * 8);
            }
            asm volatile("cp.async.commit_group;");
            asm volatile("cp.async.wait_group 1;");
        } else {
            asm volatile("cp.async.wait_group 0;");
        }
        __syncthreads();

        const uint32_t* Kw = (const uint32_t*)(Ks + st * 64 * QS);
        const uint32_t* Vw = (const uint32_t*)(Vt + st * 64 * QS);

        // S = Q @ K^T (log2-domain logits; Q carries scale*log2e)
        float sc[8][4];
        #pragma unroll
        for (int j = 0; j < 8; j++) {
            #pragma unroll
            for (int i = 0; i < 4; i++) sc[j][i] = 0.0f;
            const int n = j * 8 + (lane >> 2);
            #pragma unroll
            for (int ka = 0; ka < 4; ka++) {
                uint32_t b[2];
                b[0] = Kw[n * 36 + ka * 8 + (lane & 3)];
                b[1] = Kw[n * 36 + ka * 8 + 4 + (lane & 3)];
                mma_bf16(sc[j], qf[ka], b);
            }
        }

        // online softmax (base-2)
        float tm0 = -1e30f, tm1 = -1e30f;
        #pragma unroll
        for (int j = 0; j < 8; j++) {
            tm0 = fmaxf(tm0, fmaxf(sc[j][0], sc[j][1]));
            tm1 = fmaxf(tm1, fmaxf(sc[j][2], sc[j][3]));
        }
        tm0 = fmaxf(tm0, __shfl_xor_sync(0xFFFFFFFFu, tm0, 1));
        tm0 = fmaxf(tm0, __shfl_xor_sync(0xFFFFFFFFu, tm0, 2));
        tm1 = fmaxf(tm1, __shfl_xor_sync(0xFFFFFFFFu, tm1, 1));
        tm1 = fmaxf(tm1, __shfl_xor_sync(0xFFFFFFFFu, tm1, 2));
        const float nm0 = fmaxf(m0, tm0), nm1 = fmaxf(m1, tm1);
        const float c0 = ex2(m0 - nm0), c1 = ex2(m1 - nm1);
        m0 = nm0; m1 = nm1; l0 *= c0; l1 *= c1;
        #pragma unroll
        for (int j = 0; j < 8; j++) {
            sc[j][0] = ex2(sc[j][0] - m0);
            sc[j][1] = ex2(sc[j][1] - m0);
            sc[j][2] = ex2(sc[j][2] - m1);
            sc[j][3] = ex2(sc[j][3] - m1);
            l0 += sc[j][0] + sc[j][1];
            l1 += sc[j][2] + sc[j][3];
        }
        #pragma unroll
        for (int d = 0; d < 8; d++) {
            o[d][0] *= c0; o[d][1] *= c0; o[d][2] *= c1; o[d][3] *= c1;
        }

        // O += P @ V : C-fragments pack directly into A-fragments (bf16 k16)
        #pragma unroll
        for (int s = 0; s < 4; s++) {
            uint32_t a[4];
            a[0] = packbf(sc[2 * s][0], sc[2 * s][1]);
            a[1] = packbf(sc[2 * s][2], sc[2 * s][3]);
            a[2] = packbf(sc[2 * s + 1][0], sc[2 * s + 1][1]);
            a[3] = packbf(sc[2 * s + 1][2], sc[2 * s + 1][3]);
            #pragma unroll
            for (int d = 0; d < 8; d++) {
                const int col = d * 8 + (lane >> 2);
                uint32_t b[2];
                b[0] = Vw[col * 36 + s * 8 + (lane & 3)];
                b[1] = Vw[col * 36 + s * 8 + 4 + (lane & 3)];
                mma_bf16(o[d], a, b);
            }
        }
        __syncthreads();
    }

    l0 += __shfl_xor_sync(0xFFFFFFFFu, l0, 1);
    l0 += __shfl_xor_sync(0xFFFFFFFFu, l0, 2);
    l1 += __shfl_xor_sync(0xFFFFFFFFu, l1, 1);
    l1 += __shfl_xor_sync(0xFFFFFFFFu, l1, 2);
    const float i0 = 1.0f / l0, i1 = 1.0f / l1;

    const int r0 = qt * 128 + wid * 16 + (lane >> 2);
    float* op0 = g_o + ((long)bb * Nc) * Dc + hh * HDc + (long)r0 * Dc;
    float* op1 = op0 + 8 * Dc;
    #pragma unroll
    for (int d = 0; d < 8; d++) {
        const int col = d * 8 + 2 * (lane & 3);
        float2 w0, w1;
        w0.x = rtf32(o[d][0] * i0); w0.y = rtf32(o[d][1] * i0);
        w1.x = rtf32(o[d][2] * i1); w1.y = rtf32(o[d][3] * i1);
        *(float2*)(op0 + col) = w0;
        *(float2*)(op1 + col) = w1;
    }
}

// ---------------- driver ----------------
extern "C" void kernel_launch(void* const* d_in, const int* in_sizes, int n_in,
                              void* d_out, int out_size) {
    const float* x    = (const float*)d_in[0];
    const float* Wq   = (const float*)d_in[1];
    const float* Wk   = (const float*)d_in[2];
    const float* Wv   = (const float*)d_in[3];
    const float* Wo   = (const float*)d_in[4];
    const float* bo   = (const float*)d_in[5];
    const float* ln1g = (const float*)d_in[6];
    const float* ln1b = (const float*)d_in[7];
    const float* W1   = (const float*)d_in[8];
    const float* b1   = (const float*)d_in[9];
    const float* W2   = (const float*)d_in[10];
    const float* b2   = (const float*)d_in[11];
    const float* ln2g = (const float*)d_in[12];
    const float* ln2b = (const float*)d_in[13];
    float* h = (float*)d_out;

    float *py, *po, *pt, *pw;
    cudaGetSymbolAddress((void**)&py, g_y);
    cudaGetSymbolAddress((void**)&po, g_o);
    cudaGetSymbolAddress((void**)&pt, g_t);
    cudaGetSymbolAddress((void**)&pw, g_wr);

    const int smemProj = (2 * 128 * 36 + 2 * 32 * 136) * 4;  // 71680
    const int smemAttn = (128 * 72 + 4 * 64 * 72) * 2;       // 55296
    cudaFuncSetAttribute(gemm_pipe<0, 1>, cudaFuncAttributeMaxDynamicSharedMemorySize, smemProj);
    cudaFuncSetAttribute(gemm_pipe<1, 0>, cudaFuncAttributeMaxDynamicSharedMemorySize, smemProj);
    cudaFuncSetAttribute(gemm_pipe<2, 1>, cudaFuncAttributeMaxDynamicSharedMemorySize, smemProj);
    cudaFuncSetAttribute(qkv_gemm, cudaFuncAttributeMaxDynamicSharedMemorySize, smemProj);
    cudaFuncSetAttribute(fattn_kernel, cudaFuncAttributeMaxDynamicSharedMemorySize, smemAttn);

    cudaMemcpyAsync(h, x, sizeof(float) * (size_t)Mrows * Dc, cudaMemcpyDeviceToDevice);

    const int WSZ = Lc * Dc * Dc;
    round_kernel<<<WSZ / 1024, 256>>>(Wq, pw + 0L * WSZ);
    round_kernel<<<WSZ / 1024, 256>>>(Wk, pw + 1L * WSZ);
    round_kernel<<<WSZ / 1024, 256>>>(Wv, pw + 2L * WSZ);
    round_kernel<<<WSZ / 1024, 256>>>(Wo, pw + 3L * WSZ);
    round_kernel<<<WSZ / 1024, 256>>>(W1, pw + 4L * WSZ);
    round_kernel<<<WSZ / 1024, 256>>>(W2, pw + 5L * WSZ);

    const dim3 gProj(Dc / 128, Mrows / 128, 1);     // (4, 64)
    const dim3 gQKV(Dc / 128, Mrows / 128, 3);      // (4, 64, 3)
    const dim3 gAttn(Nc / 128, Hc, Bc);             // (16, 8, 4)

    for (int l = 0; l < Lc; l++) {
        const float* wq = pw + 0L * WSZ + (long)l * Dc * Dc;
        const float* wk = pw + 1L * WSZ + (long)l * Dc * Dc;
        const float* wv = pw + 2L * WSZ + (long)l * Dc * Dc;
        const float* wo = pw + 3L * WSZ + (long)l * Dc * Dc;
        const float* w1 = pw + 4L * WSZ + (long)l * Dc * Dc;
        const float* w2 = pw + 5L * WSZ + (long)l * Dc * Dc;

        ln_kernel<<<Mrows, 128>>>(h, ln1g + l * Dc, ln1b + l * Dc, py);
        qkv_gemm<<<gQKV, 256, smemProj>>>(py, wq, wk, wv);
        fattn_kernel<<<gAttn, 256, smemAttn>>>();
        gemm_pipe<1, 0><<<gProj, 256, smemProj>>>(po, wo, h, bo + l * Dc, h);
        ln_kernel<<<Mrows, 128>>>(h, ln2g + l * Dc, ln2b + l * Dc, py);
        gemm_pipe<2, 1><<<gProj, 256, smemProj>>>(py, w1, pt, b1 + l * Dc, nullptr);
        gemm_pipe<1, 0><<<gProj, 256, smemProj>>>(pt, w2, h, b2 + l * Dc, h);
    }
}

// round 6
// speedup vs baseline: 7.1751x; 1.1687x over previous
#include <cuda_runtime.h>
#include <cuda_bf16.h>
#include <math.h>
#include <stdint.h>

#define Lc 4
#define Bc 4
#define Nc 2048
#define Dc 512
#define Hc 8
#define HDc 64
#define Mrows (Bc*Nc)   // 8192
#define DD (Dc*Dc)

// ---------------- scratch ----------------
__device__ float g_y[Mrows*Dc];                    // fp32 LN out (FF path)
__device__ float g_t[Mrows*Dc];                    // FF hidden
__device__ float g_wr[2*Lc*DD];                    // tf32-rounded W1,W2
__device__ __nv_bfloat16 g_wt[4*Lc*DD];            // transposed bf16 Wq,Wk,Wv,Wo [n][k]
__device__ __nv_bfloat16 g_yb[Mrows*Dc];           // bf16 LN out (QKV path)
__device__ __nv_bfloat16 g_ob[Mrows*Dc];           // bf16 attention out
__device__ __nv_bfloat16 g_qb[Mrows*Dc];           // Q (pre-scaled, bf16)
__device__ __nv_bfloat16 g_kb[Mrows*Dc];           // K bf16
__device__ __nv_bfloat16 g_vt[Mrows*Dc];           // V bf16, per-(b,h) transposed [64][2048]

__device__ __forceinline__ float rtf32(float x) {
    uint32_t u;
    asm("cvt.rna.tf32.f32 %0, %1;" : "=r"(u) : "f"(x));
    return __uint_as_float(u);
}
__device__ __forceinline__ float gelu_exact(float x) {
    return 0.5f * x * (1.0f + erff(x * 0.70710678118654752f));
}
__device__ __forceinline__ float ex2(float x) {
    float r;
    asm("ex2.approx.f32 %0, %1;" : "=f"(r) : "f"(x));
    return r;
}
__device__ __forceinline__ void cpasync16(void* sdst, const void* gsrc) {
    uint32_t s = (uint32_t)__cvta_generic_to_shared(sdst);
    asm volatile("cp.async.cg.shared.global [%0], [%1], 16;" :: "r"(s), "l"(gsrc));
}
__device__ __forceinline__ void mma_tf32(float* d, const uint32_t* a, const uint32_t* b) {
    asm volatile("mma.sync.aligned.m16n8k8.row.col.f32.tf32.tf32.f32 "
                 "{%0,%1,%2,%3}, {%4,%5,%6,%7}, {%8,%9}, {%0,%1,%2,%3};"
                 : "+f"(d[0]), "+f"(d[1]), "+f"(d[2]), "+f"(d[3])
                 : "r"(a[0]), "r"(a[1]), "r"(a[2]), "r"(a[3]), "r"(b[0]), "r"(b[1]));
}
__device__ __forceinline__ void mma_bf16(float* d, const uint32_t* a, const uint32_t* b) {
    asm volatile("mma.sync.aligned.m16n8k16.row.col.f32.bf16.bf16.f32 "
                 "{%0,%1,%2,%3}, {%4,%5,%6,%7}, {%8,%9}, {%0,%1,%2,%3};"
                 : "+f"(d[0]), "+f"(d[1]), "+f"(d[2]), "+f"(d[3])
                 : "r"(a[0]), "r"(a[1]), "r"(a[2]), "r"(a[3]), "r"(b[0]), "r"(b[1]));
}
__device__ __forceinline__ uint32_t packbf(float lo, float hi) {
    __nv_bfloat162 p = __floats2bfloat162_rn(lo, hi);
    return *(uint32_t*)&p;
}

// ---------------- prep: tf32 rounding (W1,W2) ----------------
__global__ __launch_bounds__(256) void round_kernel(const float* __restrict__ in,
                                                    float* __restrict__ out) {
    const int i = blockIdx.x * 256 + threadIdx.x;
    const float4 v = ((const float4*)in)[i];
    float4 r;
    r.x = rtf32(v.x); r.y = rtf32(v.y); r.z = rtf32(v.z); r.w = rtf32(v.w);
    ((float4*)out)[i] = r;
}

// ---------------- prep: transpose [k][n] fp32 -> [n][k] bf16 ----------------
__global__ __launch_bounds__(256) void transpose_bf16(const float* __restrict__ in,
                                                      __nv_bfloat16* __restrict__ out) {
    __shared__ float t[32][33];
    const int l = blockIdx.z;
    const float* src = in + (long)l * DD;
    __nv_bfloat16* dst = out + (long)l * DD;
    const int n0 = blockIdx.x * 32, k0 = blockIdx.y * 32;
    const int tx = threadIdx.x & 31, ty = threadIdx.x >> 5;
    #pragma unroll
    for (int i = 0; i < 4; i++)
        t[ty + 8 * i][tx] = src[(long)(k0 + ty + 8 * i) * Dc + n0 + tx];
    __syncthreads();
    #pragma unroll
    for (int i = 0; i < 4; i++)
        dst[(long)(n0 + ty + 8 * i) * Dc + k0 + tx] = __float2bfloat16(t[tx][ty + 8 * i]);
}

// ---------------- LayerNorm: BF=1 -> bf16 out, else fp32 (tf32-rounded) ----------------
template <int BF>
__global__ __launch_bounds__(128) void ln_kernel(const float* __restrict__ hin,
                                                 const float* __restrict__ gg,
                                                 const float* __restrict__ bb,
                                                 void* __restrict__ yout) {
    const int row = blockIdx.x;
    const int t = threadIdx.x;
    const float4 v = ((const float4*)(hin + (size_t)row * Dc))[t];
    float s  = v.x + v.y + v.z + v.w;
    float ss = v.x*v.x + v.y*v.y + v.z*v.z + v.w*v.w;
    #pragma unroll
    for (int o = 16; o > 0; o >>= 1) {
        s  += __shfl_xor_sync(0xFFFFFFFFu, s, o);
        ss += __shfl_xor_sync(0xFFFFFFFFu, ss, o);
    }
    __shared__ float sh[8];
    const int w = t >> 5;
    if ((t & 31) == 0) { sh[w] = s; sh[4 + w] = ss; }
    __syncthreads();
    const float st  = sh[0] + sh[1] + sh[2] + sh[3];
    const float sst = sh[4] + sh[5] + sh[6] + sh[7];
    const float mu  = st * (1.0f / Dc);
    const float var = sst * (1.0f / Dc) - mu * mu;
    const float inv = rsqrtf(var + 1e-5f);
    const float4 g4 = ((const float4*)gg)[t];
    const float4 b4 = ((const float4*)bb)[t];
    const float r0 = (v.x - mu) * inv * g4.x + b4.x;
    const float r1 = (v.y - mu) * inv * g4.y + b4.y;
    const float r2 = (v.z - mu) * inv * g4.z + b4.z;
    const float r3 = (v.w - mu) * inv * g4.w + b4.w;
    if (BF) {
        uint2 p;
        p.x = packbf(r0, r1);
        p.y = packbf(r2, r3);
        ((uint2*)((__nv_bfloat16*)yout + (size_t)row * Dc))[t] = p;
    } else {
        float4 r;
        r.x = rtf32(r0); r.y = rtf32(r1); r.z = rtf32(r2); r.w = rtf32(r3);
        ((float4*)((float*)yout + (size_t)row * Dc))[t] = r;
    }
}

struct GemmCtx { int lane, wid, wm, wn, m0, n0; };

// ================= tf32 GEMM mainloop (BM=128, BN=128, BK=32) =================
__device__ __forceinline__ void gemm_mainloop(const float* __restrict__ A, int lda,
                                              const float* __restrict__ Bm, int ldb,
                                              int K, float* smem, GemmCtx& cx,
                                              float acc[2][8][4]) {
    constexpr int BM = 128, BK = 32, BN = 128;
    constexpr int AS = BK + 4, BS = BN + 8;
    float* As = smem;
    float* Bs = smem + 2 * BM * AS;

    const int tid = threadIdx.x;
    cx.lane = tid & 31; cx.wid = tid >> 5;
    cx.wm = (cx.wid >> 1) * 32; cx.wn = (cx.wid & 1) * 64;
    cx.m0 = blockIdx.y * BM; cx.n0 = blockIdx.x * BN;

    const int ar = tid >> 3, ac4 = tid & 7;
    const int br = tid >> 5, bc4 = tid & 31;

    const float* Ag = A + (long)(cx.m0 + ar) * lda + ac4 * 4;
    const float* Bg = Bm + (long)br * ldb + cx.n0 + bc4 * 4;

    #pragma unroll
    for (int mi = 0; mi < 2; mi++)
        #pragma unroll
        for (int ni = 0; ni < 8; ni++)
            #pragma unroll
            for (int j = 0; j < 4; j++) acc[mi][ni][j] = 0.0f;

    const int KT = K / BK;
    {
        #pragma unroll
        for (int i = 0; i < 4; i++)
            cpasync16(&As[(ar + 32 * i) * AS + ac4 * 4], Ag + (long)(32 * i) * lda);
        #pragma unroll
        for (int i = 0; i < 4; i++)
            cpasync16(&Bs[(br + 8 * i) * BS + bc4 * 4], Bg + (long)(8 * i) * ldb);
        asm volatile("cp.async.commit_group;");
    }

    for (int kt = 0; kt < KT; kt++) {
        const int st = kt & 1;
        if (kt + 1 < KT) {
            const int sn = st ^ 1;
            const float* Agn = Ag + (kt + 1) * BK;
            const float* Bgn = Bg + (long)(kt + 1) * BK * ldb;
            #pragma unroll
            for (int i = 0; i < 4; i++)
                cpasync16(&As[sn * BM * AS + (ar + 32 * i) * AS + ac4 * 4],
                          Agn + (long)(32 * i) * lda);
            #pragma unroll
            for (int i = 0; i < 4; i++)
                cpasync16(&Bs[sn * BK * BS + (br + 8 * i) * BS + bc4 * 4],
                          Bgn + (long)(8 * i) * ldb);
            asm volatile("cp.async.commit_group;");
            asm volatile("cp.async.wait_group 1;");
        } else {
            asm volatile("cp.async.wait_group 0;");
        }
        __syncthreads();

        const float* A0 = As + st * BM * AS;
        const float* B0 = Bs + st * BK * BS;
        #pragma unroll
        for (int kk = 0; kk < BK; kk += 8) {
            uint32_t af[2][4];
            #pragma unroll
            for (int mi = 0; mi < 2; mi++) {
                const int r = cx.wm + mi * 16 + (cx.lane >> 2);
                const int c = kk + (cx.lane & 3);
                af[mi][0] = __float_as_uint(A0[r * AS + c]);
                af[mi][1] = __float_as_uint(A0[(r + 8) * AS + c]);
                af[mi][2] = __float_as_uint(A0[r * AS + c + 4]);
                af[mi][3] = __float_as_uint(A0[(r + 8) * AS + c + 4]);
            }
            uint32_t bf[8][2];
            #pragma unroll
            for (int ni = 0; ni < 8; ni++) {
                const int col = cx.wn + ni * 8 + (cx.lane >> 2);
                const int kr = kk + (cx.lane & 3);
                bf[ni][0] = __float_as_uint(B0[kr * BS + col]);
                bf[ni][1] = __float_as_uint(B0[(kr + 4) * BS + col]);
            }
            #pragma unroll
            for (int mi = 0; mi < 2; mi++)
                #pragma unroll
                for (int ni = 0; ni < 8; ni++)
                    mma_tf32(acc[mi][ni], af[mi], bf[ni]);
        }
        __syncthreads();
    }
}

// ================= bf16 GEMM mainloop (BM=128, BN=128, BK=32) =================
// A row-major [m][k] bf16, B pre-transposed [n][k] bf16 (both k-contiguous).
__device__ __forceinline__ void bf16_mainloop(const __nv_bfloat16* __restrict__ A,
                                              const __nv_bfloat16* __restrict__ Bt,
                                              uint32_t* smw, GemmCtx& cx,
                                              float acc[2][8][4]) {
    constexpr int RW = 20;  // words per smem row (32 bf16 + 8 pad)
    uint32_t* As = smw;                 // [2][128][20]
    uint32_t* Bs = smw + 2 * 128 * RW;  // [2][128][20]

    const int tid = threadIdx.x;
    cx.lane = tid & 31; cx.wid = tid >> 5;
    cx.wm = (cx.wid >> 1) * 32; cx.wn = (cx.wid & 1) * 64;
    cx.m0 = blockIdx.y * 128; cx.n0 = blockIdx.x * 128;

    #pragma unroll
    for (int mi = 0; mi < 2; mi++)
        #pragma unroll
        for (int ni = 0; ni < 8; ni++)
            #pragma unroll
            for (int j = 0; j < 4; j++) acc[mi][ni][j] = 0.0f;

    // loader: 512 chunks of 16B per tile -> 2 per thread
    const int r0l = (tid) >> 2, ch0 = (tid & 3);
    const int r1l = (tid + 256) >> 2, ch1 = ((tid + 256) & 3);

    const __nv_bfloat16* Ag = A + (long)cx.m0 * Dc;
    const __nv_bfloat16* Bg = Bt + (long)cx.n0 * Dc;

    {
        cpasync16(&As[r0l * RW + ch0 * 4], Ag + (long)r0l * Dc + ch0 * 8);
        cpasync16(&As[r1l * RW + ch1 * 4], Ag + (long)r1l * Dc + ch1 * 8);
        cpasync16(&Bs[r0l * RW + ch0 * 4], Bg + (long)r0l * Dc + ch0 * 8);
        cpasync16(&Bs[r1l * RW + ch1 * 4], Bg + (long)r1l * Dc + ch1 * 8);
        asm volatile("cp.async.commit_group;");
    }

    const int KT = Dc / 32;
    for (int kt = 0; kt < KT; kt++) {
        const int st = kt & 1;
        if (kt + 1 < KT) {
            const int sn = st ^ 1;
            const int ko = (kt + 1) * 32;
            cpasync16(&As[sn * 128 * RW + r0l * RW + ch0 * 4], Ag + (long)r0l * Dc + ko + ch0 * 8);
            cpasync16(&As[sn * 128 * RW + r1l * RW + ch1 * 4], Ag + (long)r1l * Dc + ko + ch1 * 8);
            cpasync16(&Bs[sn * 128 * RW + r0l * RW + ch0 * 4], Bg + (long)r0l * Dc + ko + ch0 * 8);
            cpasync16(&Bs[sn * 128 * RW + r1l * RW + ch1 * 4], Bg + (long)r1l * Dc + ko + ch1 * 8);
            asm volatile("cp.async.commit_group;");
            asm volatile("cp.async.wait_group 1;");
        } else {
            asm volatile("cp.async.wait_group 0;");
        }
        __syncthreads();

        const uint32_t* A0 = As + st * 128 * RW;
        const uint32_t* B0 = Bs + st * 128 * RW;
        #pragma unroll
        for (int s = 0; s < 2; s++) {
            uint32_t af[2][4];
            #pragma unroll
            for (int mi = 0; mi < 2; mi++) {
                const int r = cx.wm + mi * 16 + (cx.lane >> 2);
                const int c = s * 8 + (cx.lane & 3);
                af[mi][0] = A0[r * RW + c];
                af[mi][1] = A0[(r + 8) * RW + c];
                af[mi][2] = A0[r * RW + c + 4];
                af[mi][3] = A0[(r + 8) * RW + c + 4];
            }
            uint32_t bf[8][2];
            #pragma unroll
            for (int ni = 0; ni < 8; ni++) {
                const int n = cx.wn + ni * 8 + (cx.lane >> 2);
                const int c = s * 8 + (cx.lane & 3);
                bf[ni][0] = B0[n * RW + c];
                bf[ni][1] = B0[n * RW + c + 4];
            }
            #pragma unroll
            for (int mi = 0; mi < 2; mi++)
                #pragma unroll
                for (int ni = 0; ni < 8; ni++)
                    mma_bf16(acc[mi][ni], af[mi], bf[ni]);
        }
        __syncthreads();
    }
}

// ---------------- tf32 GEMM with fp32 epilogue (FF path) ----------------
// OP 1: C = resid + acc + bias ; OP 2: C = gelu(acc + bias)
template <int OP, int RND>
__global__ __launch_bounds__(256)
void gemm_pipe(const float* __restrict__ A, const float* __restrict__ Bm,
               float* __restrict__ C,
               const float* __restrict__ bias, const float* __restrict__ resid) {
    extern __shared__ float smem[];
    GemmCtx cx;
    float acc[2][8][4];
    gemm_mainloop(A, Dc, Bm, Dc, Dc, smem, cx, acc);

    #pragma unroll
    for (int mi = 0; mi < 2; mi++) {
        const int r0 = cx.m0 + cx.wm + mi * 16 + (cx.lane >> 2);
        #pragma unroll
        for (int ni = 0; ni < 8; ni++) {
            const int col = cx.n0 + cx.wn + ni * 8 + (cx.lane & 3) * 2;
            #pragma unroll
            for (int half = 0; half < 2; half++) {
                const int r = r0 + half * 8;
                float v0 = acc[mi][ni][half * 2 + 0];
                float v1 = acc[mi][ni][half * 2 + 1];
                if (OP == 1) {
                    const float2 rs = *(const float2*)(resid + (long)r * Dc + col);
                    v0 = rs.x + v0 + bias[col];
                    v1 = rs.y + v1 + bias[col + 1];
                } else {
                    v0 = gelu_exact(v0 + bias[col]);
                    v1 = gelu_exact(v1 + bias[col + 1]);
                }
                if (RND) { v0 = rtf32(v0); v1 = rtf32(v1); }
                float2 w2; w2.x = v0; w2.y = v1;
                *(float2*)(C + (long)r * Dc + col) = w2;
            }
        }
    }
}

// ---------------- QKV bf16 GEMM: z selects weight + output layout ----------------
#define QSC 0.06376237f  /* 512^-0.5 * log2(e) */
__global__ __launch_bounds__(256)
void qkv_gemm(const __nv_bfloat16* __restrict__ A, const __nv_bfloat16* __restrict__ wqt,
              const __nv_bfloat16* __restrict__ wkt, const __nv_bfloat16* __restrict__ wvt) {
    extern __shared__ uint32_t smw[];
    const int z = blockIdx.z;
    const __nv_bfloat16* W = (z == 0) ? wqt : (z == 1) ? wkt : wvt;
    GemmCtx cx;
    float acc[2][8][4];
    bf16_mainloop(A, W, smw, cx, acc);

    #pragma unroll
    for (int mi = 0; mi < 2; mi++) {
        const int r0 = cx.m0 + cx.wm + mi * 16 + (cx.lane >> 2);
        #pragma unroll
        for (int ni = 0; ni < 8; ni++) {
            const int col = cx.n0 + cx.wn + ni * 8 + (cx.lane & 3) * 2;
            #pragma unroll
            for (int half = 0; half < 2; half++) {
                const int r = r0 + half * 8;
                const float v0 = acc[mi][ni][half * 2 + 0];
                const float v1 = acc[mi][ni][half * 2 + 1];
                if (z == 0) {
                    *(uint32_t*)(g_qb + (long)r * Dc + col) = packbf(v0 * QSC, v1 * QSC);
                } else if (z == 1) {
                    *(uint32_t*)(g_kb + (long)r * Dc + col) = packbf(v0, v1);
                } else {
                    const int bidx = r >> 11, tok = r & 2047;
                    const long hb = ((long)bidx * Hc + (col >> 6)) * (HDc * Nc);
                    g_vt[hb + (long)(col & 63) * Nc + tok] = __float2bfloat16(v0);
                    g_vt[hb + (long)((col + 1) & 63) * Nc + tok] = __float2bfloat16(v1);
                }
            }
        }
    }
}

// ---------------- Wo bf16 GEMM: h = resid + o@Wo + bias ----------------
__global__ __launch_bounds__(256)
void wo_gemm(const __nv_bfloat16* __restrict__ A, const __nv_bfloat16* __restrict__ wot,
             float* __restrict__ C, const float* __restrict__ bias,
             const float* __restrict__ resid) {
    extern __shared__ uint32_t smw[];
    GemmCtx cx;
    float acc[2][8][4];
    bf16_mainloop(A, wot, smw, cx, acc);

    #pragma unroll
    for (int mi = 0; mi < 2; mi++) {
        const int r0 = cx.m0 + cx.wm + mi * 16 + (cx.lane >> 2);
        #pragma unroll
        for (int ni = 0; ni < 8; ni++) {
            const int col = cx.n0 + cx.wn + ni * 8 + (cx.lane & 3) * 2;
            #pragma unroll
            for (int half = 0; half < 2; half++) {
                const int r = r0 + half * 8;
                const float2 rs = *(const float2*)(resid + (long)r * Dc + col);
                float2 w2;
                w2.x = rs.x + acc[mi][ni][half * 2 + 0] + bias[col];
                w2.y = rs.y + acc[mi][ni][half * 2 + 1] + bias[col + 1];
                *(float2*)(C + (long)r * Dc + col) = w2;
            }
        }
    }
}

// ---------------- bf16 fused flash attention ----------------
__global__ __launch_bounds__(256, 2) void fattn_kernel() {
    constexpr int QS = 72;
    extern __shared__ __align__(16) char smraw[];
    __nv_bfloat16* Qs = (__nv_bfloat16*)smraw;      // [128][72]
    __nv_bfloat16* Ks = Qs + 128 * QS;              // [2][64][72]
    __nv_bfloat16* Vt = Ks + 2 * 64 * QS;           // [2][64][72] (dim-major)

    const int qt = blockIdx.x, hh = blockIdx.y, bb = blockIdx.z;
    const int tid = threadIdx.x, lane = tid & 31, wid = tid >> 5;
    const long kvbase = ((long)bb * Nc) * Dc + hh * HDc;
    const long vtbase = ((long)bb * Hc + hh) * (HDc * Nc);

    #pragma unroll
    for (int i = 0; i < 4; i++) {
        const int idx = tid + 256 * i;
        const int r = idx >> 3, ch = idx & 7;
        cpasync16(&Qs[r * QS + ch * 8],
                  g_qb + kvbase + (long)(qt * 128 + r) * Dc + ch * 8);
    }
    #pragma unroll
    for (int i = 0; i < 2; i++) {
        const int idx = tid + 256 * i;
        const int r = idx >> 3, ch = idx & 7;
        cpasync16(&Ks[r * QS + ch * 8], g_kb + kvbase + (long)r * Dc + ch * 8);
        cpasync16(&Vt[r * QS + ch * 8], g_vt + vtbase + (long)r * Nc + ch * 8);
    }
    asm volatile("cp.async.commit_group;");
    asm volatile("cp.async.wait_group 0;");
    __syncthreads();

    uint32_t qf[4][4];
    {
        const uint32_t* Qw = (const uint32_t*)Qs;
        const int r0 = wid * 16 + (lane >> 2);
        #pragma unroll
        for (int ka = 0; ka < 4; ka++) {
            const int c = ka * 8 + (lane & 3);
            qf[ka][0] = Qw[r0 * 36 + c];
            qf[ka][1] = Qw[(r0 + 8) * 36 + c];
            qf[ka][2] = Qw[r0 * 36 + c + 4];
            qf[ka][3] = Qw[(r0 + 8) * 36 + c + 4];
        }
    }

    float o[8][4];
    #pragma unroll
    for (int d = 0; d < 8; d++)
        #pragma unroll
        for (int j = 0; j < 4; j++) o[d][j] = 0.0f;
    float m0 = -1e30f, m1 = -1e30f, l0 = 0.0f, l1 = 0.0f;

    for (int kt = 0; kt < Nc / 64; kt++) {
        const int st = kt & 1;
        if (kt + 1 < Nc / 64) {
            const int sn = st ^ 1;
            #pragma unroll
            for (int i = 0; i < 2; i++) {
                const int idx = tid + 256 * i;
                const int r = idx >> 3, ch = idx & 7;
                cpasync16(&Ks[sn * 64 * QS + r * QS + ch * 8],
                          g_kb + kvbase + (long)((kt + 1) * 64 + r) * Dc + ch * 8);
                cpasync16(&Vt[sn * 64 * QS + r * QS + ch * 8],
                          g_vt + vtbase + (long)r * Nc + (kt + 1) * 64 + ch * 8);
            }
            asm volatile("cp.async.commit_group;");
            asm volatile("cp.async.wait_group 1;");
        } else {
            asm volatile("cp.async.wait_group 0;");
        }
        __syncthreads();

        const uint32_t* Kw = (const uint32_t*)(Ks + st * 64 * QS);
        const uint32_t* Vw = (const uint32_t*)(Vt + st * 64 * QS);

        float sc[8][4];
        #pragma unroll
        for (int j = 0; j < 8; j++) {
            #pragma unroll
            for (int i = 0; i < 4; i++) sc[j][i] = 0.0f;
            const int n = j * 8 + (lane >> 2);
            #pragma unroll
            for (int ka = 0; ka < 4; ka++) {
                uint32_t b[2];
                b[0] = Kw[n * 36 + ka * 8 + (lane & 3)];
                b[1] = Kw[n * 36 + ka * 8 + 4 + (lane & 3)];
                mma_bf16(sc[j], qf[ka], b);
            }
        }

        float tm0 = -1e30f, tm1 = -1e30f;
        #pragma unroll
        for (int j = 0; j < 8; j++) {
            tm0 = fmaxf(tm0, fmaxf(sc[j][0], sc[j][1]));
            tm1 = fmaxf(tm1, fmaxf(sc[j][2], sc[j][3]));
        }
        tm0 = fmaxf(tm0, __shfl_xor_sync(0xFFFFFFFFu, tm0, 1));
        tm0 = fmaxf(tm0, __shfl_xor_sync(0xFFFFFFFFu, tm0, 2));
        tm1 = fmaxf(tm1, __shfl_xor_sync(0xFFFFFFFFu, tm1, 1));
        tm1 = fmaxf(tm1, __shfl_xor_sync(0xFFFFFFFFu, tm1, 2));
        const float nm0 = fmaxf(m0, tm0), nm1 = fmaxf(m1, tm1);
        const float c0 = ex2(m0 - nm0), c1 = ex2(m1 - nm1);
        m0 = nm0; m1 = nm1; l0 *= c0; l1 *= c1;
        #pragma unroll
        for (int j = 0; j < 8; j++) {
            sc[j][0] = ex2(sc[j][0] - m0);
            sc[j][1] = ex2(sc[j][1] - m0);
            sc[j][2] = ex2(sc[j][2] - m1);
            sc[j][3] = ex2(sc[j][3] - m1);
            l0 += sc[j][0] + sc[j][1];
            l1 += sc[j][2] + sc[j][3];
        }
        #pragma unroll
        for (int d = 0; d < 8; d++) {
            o[d][0] *= c0; o[d][1] *= c0; o[d][2] *= c1; o[d][3] *= c1;
        }

        #pragma unroll
        for (int s = 0; s < 4; s++) {
            uint32_t a[4];
            a[0] = packbf(sc[2 * s][0], sc[2 * s][1]);
            a[1] = packbf(sc[2 * s][2], sc[2 * s][3]);
            a[2] = packbf(sc[2 * s + 1][0], sc[2 * s + 1][1]);
            a[3] = packbf(sc[2 * s + 1][2], sc[2 * s + 1][3]);
            #pragma unroll
            for (int d = 0; d < 8; d++) {
                const int col = d * 8 + (lane >> 2);
                uint32_t b[2];
                b[0] = Vw[col * 36 + s * 8 + (lane & 3)];
                b[1] = Vw[col * 36 + s * 8 + 4 + (lane & 3)];
                mma_bf16(o[d], a, b);
            }
        }
        __syncthreads();
    }

    l0 += __shfl_xor_sync(0xFFFFFFFFu, l0, 1);
    l0 += __shfl_xor_sync(0xFFFFFFFFu, l0, 2);
    l1 += __shfl_xor_sync(0xFFFFFFFFu, l1, 1);
    l1 += __shfl_xor_sync(0xFFFFFFFFu, l1, 2);
    const float i0 = 1.0f / l0, i1 = 1.0f / l1;

    const int r0 = qt * 128 + wid * 16 + (lane >> 2);
    __nv_bfloat16* op0 = g_ob + ((long)bb * Nc) * Dc + hh * HDc + (long)r0 * Dc;
    __nv_bfloat16* op1 = op0 + 8 * Dc;
    #pragma unroll
    for (int d = 0; d < 8; d++) {
        const int col = d * 8 + 2 * (lane & 3);
        *(uint32_t*)(op0 + col) = packbf(o[d][0] * i0, o[d][1] * i0);
        *(uint32_t*)(op1 + col) = packbf(o[d][2] * i1, o[d][3] * i1);
    }
}

// ---------------- driver ----------------
extern "C" void kernel_launch(void* const* d_in, const int* in_sizes, int n_in,
                              void* d_out, int out_size) {
    const float* x    = (const float*)d_in[0];
    const float* Wq   = (const float*)d_in[1];
    const float* Wk   = (const float*)d_in[2];
    const float* Wv   = (const float*)d_in[3];
    const float* Wo   = (const float*)d_in[4];
    const float* bo   = (const float*)d_in[5];
    const float* ln1g = (const float*)d_in[6];
    const float* ln1b = (const float*)d_in[7];
    const float* W1   = (const float*)d_in[8];
    const float* b1   = (const float*)d_in[9];
    const float* W2   = (const float*)d_in[10];
    const float* b2   = (const float*)d_in[11];
    const float* ln2g = (const float*)d_in[12];
    const float* ln2b = (const float*)d_in[13];
    float* h = (float*)d_out;

    float *py, *pt, *pw;
    __nv_bfloat16 *pwt, *pyb, *pob;
    cudaGetSymbolAddress((void**)&py, g_y);
    cudaGetSymbolAddress((void**)&pt, g_t);
    cudaGetSymbolAddress((void**)&pw, g_wr);
    cudaGetSymbolAddress((void**)&pwt, g_wt);
    cudaGetSymbolAddress((void**)&pyb, g_yb);
    cudaGetSymbolAddress((void**)&pob, g_ob);

    const int smemProj = (2 * 128 * 36 + 2 * 32 * 136) * 4;  // 71680
    const int smemBF   = 4 * 128 * 20 * 4;                   // 40960
    const int smemAttn = (128 * 72 + 4 * 64 * 72) * 2;       // 55296
    cudaFuncSetAttribute(gemm_pipe<1, 0>, cudaFuncAttributeMaxDynamicSharedMemorySize, smemProj);
    cudaFuncSetAttribute(gemm_pipe<2, 1>, cudaFuncAttributeMaxDynamicSharedMemorySize, smemProj);
    cudaFuncSetAttribute(fattn_kernel, cudaFuncAttributeMaxDynamicSharedMemorySize, smemAttn);

    cudaMemcpyAsync(h, x, sizeof(float) * (size_t)Mrows * Dc, cudaMemcpyDeviceToDevice);

    // prep: round FF weights to tf32; transpose attention weights to bf16 [n][k]
    const int WSZ = Lc * DD;
    round_kernel<<<WSZ / 1024, 256>>>(W1, pw + 0L * WSZ);
    round_kernel<<<WSZ / 1024, 256>>>(W2, pw + 1L * WSZ);
    const dim3 gT(Dc / 32, Dc / 32, Lc);
    transpose_bf16<<<gT, 256>>>(Wq, pwt + 0L * WSZ);
    transpose_bf16<<<gT, 256>>>(Wk, pwt + 1L * WSZ);
    transpose_bf16<<<gT, 256>>>(Wv, pwt + 2L * WSZ);
    transpose_bf16<<<gT, 256>>>(Wo, pwt + 3L * WSZ);

    const dim3 gProj(Dc / 128, Mrows / 128, 1);     // (4, 64)
    const dim3 gQKV(Dc / 128, Mrows / 128, 3);      // (4, 64, 3)
    const dim3 gAttn(Nc / 128, Hc, Bc);             // (16, 8, 4)

    for (int l = 0; l < Lc; l++) {
        const __nv_bfloat16* wqt = pwt + 0L * WSZ + (long)l * DD;
        const __nv_bfloat16* wkt = pwt + 1L * WSZ + (long)l * DD;
        const __nv_bfloat16* wvt = pwt + 2L * WSZ + (long)l * DD;
        const __nv_bfloat16* wot = pwt + 3L * WSZ + (long)l * DD;
        const float* w1 = pw + 0L * WSZ + (long)l * DD;
        const float* w2 = pw + 1L * WSZ + (long)l * DD;

        ln_kernel<1><<<Mrows, 128>>>(h, ln1g + l * Dc, ln1b + l * Dc, pyb);
        qkv_gemm<<<gQKV, 256, smemBF>>>(pyb, wqt, wkt, wvt);
        fattn_kernel<<<gAttn, 256, smemAttn>>>();
        wo_gemm<<<gProj, 256, smemBF>>>(pob, wot, h, bo + l * Dc, h);
        ln_kernel<0><<<Mrows, 128>>>(h, ln2g + l * Dc, ln2b + l * Dc, py);
        gemm_pipe<2, 1><<<gProj, 256, smemProj>>>(py, w1, pt, b1 + l * Dc, nullptr);
        gemm_pipe<1, 0><<<gProj, 256, smemProj>>>(pt, w2, h, b2 + l * Dc, h);
    }
}